// round 12
// baseline (speedup 1.0000x reference)
#include <cuda_runtime.h>
#include <cuda_bf16.h>
#include <math.h>
#include <stdint.h>

#define T_SEQ 2048
#define NTOK  4096
#define DM    512
#define NH    8
#define DH    64
#define DP    32

typedef unsigned long long ull;

// ---------------- mma / async helpers ----------------------------------------
__device__ __forceinline__ uint32_t smem_u32(const void* p) {
    uint32_t a;
    asm("{ .reg .u64 t; cvta.to.shared.u64 t, %1; cvt.u32.u64 %0, t; }"
        : "=r"(a) : "l"(p));
    return a;
}
__device__ __forceinline__ void cp16(uint32_t dst, const void* src) {
    asm volatile("cp.async.cg.shared.global [%0], [%1], 16;"
        :: "r"(dst), "l"(src) : "memory");
}
__device__ __forceinline__ void ldsm4(uint32_t& r0, uint32_t& r1, uint32_t& r2,
                                      uint32_t& r3, uint32_t addr) {
    asm volatile("ldmatrix.sync.aligned.m8n8.x4.shared.b16 {%0,%1,%2,%3}, [%4];"
        : "=r"(r0), "=r"(r1), "=r"(r2), "=r"(r3) : "r"(addr));
}
__device__ __forceinline__ void mma16816(float& c0, float& c1, float& c2, float& c3,
                                         uint32_t a0, uint32_t a1, uint32_t a2,
                                         uint32_t a3, uint32_t b0, uint32_t b1) {
    asm volatile("mma.sync.aligned.m16n8k16.row.col.f32.bf16.bf16.f32 "
        "{%0,%1,%2,%3}, {%4,%5,%6,%7}, {%8,%9}, {%0,%1,%2,%3};"
        : "+f"(c0), "+f"(c1), "+f"(c2), "+f"(c3)
        : "r"(a0), "r"(a1), "r"(a2), "r"(a3), "r"(b0), "r"(b1));
}

// ---------------- scratch (device globals) ----------------------------------
__device__ __align__(16) float g_v[NTOK * DM];
__device__ __align__(16) float g_h[NTOK * DM];
__device__ __align__(16) float g_he0[NTOK * DM];
__device__ __align__(16) float g_he1[NTOK * DM];
__device__ __align__(16) float g_he2[NTOK * DM];
__device__ __align__(16) float g_cos[T_SEQ * 16];
__device__ __align__(16) float g_sin[T_SEQ * 16];

// q/k bf16 split (compact): [bh][t][64]; q = [qh|ql] (log2e folded), k = [kh|kl]
__device__ __align__(16) __nv_bfloat16 g_qs[16 * T_SEQ * 64];
__device__ __align__(16) __nv_bfloat16 g_ks[16 * T_SEQ * 64];
// transposed V splits: [bh][dim 64][t 2048]
__device__ __align__(16) __nv_bfloat16 g_vth[16 * 64 * T_SEQ];
__device__ __align__(16) __nv_bfloat16 g_vtl[16 * 64 * T_SEQ];

// activation split buffers (compact [hi|lo], 1024 cols)
__device__ __align__(16) __nv_bfloat16 g_a16[NTOK * 1024];
__device__ __align__(16) __nv_bfloat16 g_b16[NTOK * 1024];
// weight split buffers (compact [hi|lo])
__device__ __align__(16) __nv_bfloat16 g_w16qkv[1024 * 1024];  // rows 0-511 qk, 512-1023 v
__device__ __align__(16) __nv_bfloat16 g_w16p[512 * 1024];
__device__ __align__(16) __nv_bfloat16 g_w16e0[512 * 1024];
__device__ __align__(16) __nv_bfloat16 g_w16e1[512 * 1024];
__device__ __align__(16) __nv_bfloat16 g_w16e2[512 * 1024];

// ---------------- activation split of x (vectorized) -------------------------
__global__ __launch_bounds__(256) void mega_act_kernel(const float* __restrict__ x) {
    int idx4 = blockIdx.x * 256 + threadIdx.x;
    int row = idx4 >> 7, c = (idx4 & 127) * 4;
    float4 v = *(const float4*)(x + (size_t)row * 512 + c);
    size_t base = (size_t)row * 1024 + c;
    __nv_bfloat162 h01 = __floats2bfloat162_rn(v.x, v.y);
    __nv_bfloat162 h23 = __floats2bfloat162_rn(v.z, v.w);
    __nv_bfloat162 l01 = __floats2bfloat162_rn(v.x - __bfloat162float(h01.x),
                                               v.y - __bfloat162float(h01.y));
    __nv_bfloat162 l23 = __floats2bfloat162_rn(v.z - __bfloat162float(h23.x),
                                               v.w - __bfloat162float(h23.y));
    *(__nv_bfloat162*)(g_a16 + base) = h01;
    *(__nv_bfloat162*)(g_a16 + base + 2) = h23;
    *(__nv_bfloat162*)(g_a16 + base + 512) = l01;
    *(__nv_bfloat162*)(g_a16 + base + 514) = l23;
}

// ---------------- weight splits ----------------------------------------------
__global__ __launch_bounds__(256) void mega_w_kernel(
    const float* __restrict__ qp, const float* __restrict__ kp,
    const float* __restrict__ wv, const float* __restrict__ wproj,
    const float* __restrict__ ew0, const float* __restrict__ ew1,
    const float* __restrict__ ew2)
{
    int blk = blockIdx.x, tid = threadIdx.x;
    if (blk < 2048) {
        int idx = blk * 256 + tid;
        int row = idx >> 9, col = idx & 511;
        float v;
        if (row < 512) {
            const float* s = (row < 256) ? qp : kp;
            int nn = row & 255;
            int hh = nn >> 5, o = nn & 31;
            v = s[hh * 16384 + col * 32 + o];
        } else {
            v = wv[(size_t)(row - 512) * 512 + col];
        }
        __nv_bfloat16 h = __float2bfloat16(v);
        size_t base = (size_t)row * 1024;
        g_w16qkv[base + col] = h;
        g_w16qkv[base + 512 + col] = __float2bfloat16(v - __bfloat162float(h));
        return;
    }
    const float* src; __nv_bfloat16* dst;
    int idx;
    if (blk < 3072)      { src = wproj; dst = g_w16p;  idx = (blk - 2048) * 256 + tid; }
    else if (blk < 4096) { src = ew0;   dst = g_w16e0; idx = (blk - 3072) * 256 + tid; }
    else if (blk < 5120) { src = ew1;   dst = g_w16e1; idx = (blk - 4096) * 256 + tid; }
    else                 { src = ew2;   dst = g_w16e2; idx = (blk - 5120) * 256 + tid; }
    int row = idx >> 9, col = idx & 511;
    float v = src[idx];
    __nv_bfloat16 h = __float2bfloat16(v);
    size_t base = (size_t)row * 1024;
    dst[base + col] = h;
    dst[base + 512 + col] = __float2bfloat16(v - __bfloat162float(h));
}

// ---------------- trig table --------------------------------------------------
__global__ void trig_kernel() {
    int idx = blockIdx.x * 256 + threadIdx.x;
    if (idx >= T_SEQ * 16) return;
    int t = idx >> 4, i = idx & 15;
    double p = pow(10000.0, (double)i / 16.0);
    float pf = (float)p;
    float freq = 1.0f / pf;
    float ang = (float)t * freq;
    g_cos[idx] = (float)cos((double)ang);
    g_sin[idx] = (float)sin((double)ang);
}

// ---------------- HMMA GEMM (128x128 tile, 3-stage cp.async) -----------------
// epi: 0 none, 1 C=R+acc, 2 C=R+silu(acc),
//      3 qkv mode: bn<512 -> in-register RoPE -> g_qs/g_ks splits;
//                  bn>=512 -> C2 fp32 + transposed split to g_vth/g_vtl.
#define NKT 24
#define STG 32768
#define GSMEM (3 * STG)
__global__ __launch_bounds__(256) void gemm_mma_kernel(
    const __nv_bfloat16* __restrict__ A16, const __nv_bfloat16* __restrict__ W16,
    const float* __restrict__ R, float* __restrict__ C, float* __restrict__ C2,
    __nv_bfloat16* __restrict__ S, const float* __restrict__ gain, int epi)
{
    extern __shared__ __align__(128) char sm[];
    uint32_t sb = smem_u32(sm);

    int tid = threadIdx.x, wid = tid >> 5, lane = tid & 31;
    int bm = blockIdx.y * 128, bn = blockIdx.x * 128;
    int wm = wid >> 1, wn = wid & 1;

    const __nv_bfloat16* Abase = A16 + (size_t)bm * 1024;
    const __nv_bfloat16* Wbase = W16 + (size_t)bn * 1024;

    auto load_stage = [&](int kt) {
        uint32_t dA = sb + (uint32_t)(kt % 3) * STG;
        uint32_t dB = dA + 16384;
        int aOff = ((kt < 16) ? kt : kt - 16) * 64;
        int wOff = ((kt < 8) ? kt : kt - 8) * 64;
#pragma unroll
        for (int it = 0; it < 4; it++) {
            int idx = it * 256 + tid, row = idx >> 3, seg = idx & 7;
            uint32_t off = (uint32_t)(row * 128 + ((seg * 16) ^ ((row & 7) << 4)));
            cp16(dA + off, Abase + (size_t)row * 1024 + aOff + seg * 8);
        }
#pragma unroll
        for (int it = 0; it < 4; it++) {
            int idx = it * 256 + tid, row = idx >> 3, seg = idx & 7;
            uint32_t off = (uint32_t)(row * 128 + ((seg * 16) ^ ((row & 7) << 4)));
            cp16(dB + off, Wbase + (size_t)row * 1024 + wOff + seg * 8);
        }
        asm volatile("cp.async.commit_group;" ::: "memory");
    };

    int aRow[2]; uint32_t aSw[2];
#pragma unroll
    for (int mi = 0; mi < 2; mi++) {
        int row = wm * 32 + mi * 16 + (lane & 15);
        aRow[mi] = row;
        aSw[mi] = (uint32_t)((((lane >> 4) << 4)) ^ ((row & 7) << 4));
    }
    int bRow[4]; uint32_t bSw[4];
#pragma unroll
    for (int g = 0; g < 4; g++) {
        int nrow = wn * 64 + g * 16 + (lane & 7) + ((lane >> 4) << 3);
        bRow[g] = nrow;
        bSw[g] = (uint32_t)(((lane & 8) << 1) ^ ((nrow & 7) << 4));
    }

    float c[2][8][4];
#pragma unroll
    for (int mi = 0; mi < 2; mi++)
#pragma unroll
        for (int ni = 0; ni < 8; ni++)
#pragma unroll
            for (int q = 0; q < 4; q++) c[mi][ni][q] = 0.f;

    load_stage(0);
    load_stage(1);

    for (int kt = 0; kt < NKT; kt++) {
        if (kt < NKT - 1) {
            asm volatile("cp.async.wait_group 1;" ::: "memory");
        } else {
            asm volatile("cp.async.wait_group 0;" ::: "memory");
        }
        __syncthreads();
        if (kt + 2 < NKT) load_stage(kt + 2);
        uint32_t base = sb + (uint32_t)(kt % 3) * STG;
        uint32_t baseB = base + 16384;
#pragma unroll
        for (int ks = 0; ks < 4; ks++) {
            uint32_t a0[4], a1[4], b[4][4];
            ldsm4(a0[0], a0[1], a0[2], a0[3],
                  base + (uint32_t)(aRow[0] * 128) + (uint32_t)((ks * 32) ^ aSw[0]));
            ldsm4(a1[0], a1[1], a1[2], a1[3],
                  base + (uint32_t)(aRow[1] * 128) + (uint32_t)((ks * 32) ^ aSw[1]));
#pragma unroll
            for (int g = 0; g < 4; g++)
                ldsm4(b[g][0], b[g][1], b[g][2], b[g][3],
                      baseB + (uint32_t)(bRow[g] * 128) + (uint32_t)((ks * 32) ^ bSw[g]));
#pragma unroll
            for (int g = 0; g < 4; g++) {
                mma16816(c[0][2 * g][0], c[0][2 * g][1], c[0][2 * g][2], c[0][2 * g][3],
                         a0[0], a0[1], a0[2], a0[3], b[g][0], b[g][1]);
                mma16816(c[0][2 * g + 1][0], c[0][2 * g + 1][1], c[0][2 * g + 1][2], c[0][2 * g + 1][3],
                         a0[0], a0[1], a0[2], a0[3], b[g][2], b[g][3]);
                mma16816(c[1][2 * g][0], c[1][2 * g][1], c[1][2 * g][2], c[1][2 * g][3],
                         a1[0], a1[1], a1[2], a1[3], b[g][0], b[g][1]);
                mma16816(c[1][2 * g + 1][0], c[1][2 * g + 1][1], c[1][2 * g + 1][2], c[1][2 * g + 1][3],
                         a1[0], a1[1], a1[2], a1[3], b[g][2], b[g][3]);
            }
        }
    }

    int gq = lane >> 2, tig = lane & 3;

    if (epi == 3) {
        if (bn < 512) {
            // ---- QK half: in-register RoPE + split write to g_qs/g_ks ----
            const float SC = 0.17677669529663687f * 1.4426950408889634f;
#pragma unroll
            for (int mi = 0; mi < 2; mi++) {
#pragma unroll
                for (int half = 0; half < 2; half++) {
                    int row = bm + wm * 32 + mi * 16 + gq + half * 8;
                    int t = row & 2047, bq = row >> 11;
#pragma unroll
                    for (int ni0 = 0; ni0 < 8; ni0 += 4) {
                        int colbase = bn + wn * 64 + ni0 * 8;   // 32-aligned
                        int hd = colbase >> 5;
                        bool isq = hd < 8;
                        int hh = isq ? hd : hd - 8;
                        float gm = isq ? (gain[hh] * SC) : 1.0f;
                        __nv_bfloat16* dst = (isq ? g_qs : g_ks)
                                           + ((size_t)(bq * 8 + hh) * 2048 + t) * 64;
#pragma unroll
                        for (int j = 0; j < 2; j++) {
                            int i = j * 8 + tig * 2;
                            float x1a = c[mi][ni0 + j][half * 2];
                            float x1b = c[mi][ni0 + j][half * 2 + 1];
                            float x2a = c[mi][ni0 + j + 2][half * 2];
                            float x2b = c[mi][ni0 + j + 2][half * 2 + 1];
                            float ca = g_cos[t * 16 + i], sa = g_sin[t * 16 + i];
                            float cb = g_cos[t * 16 + i + 1], sb = g_sin[t * 16 + i + 1];
                            float o1a = (x1a * ca - x2a * sa) * gm;
                            float o1b = (x1b * cb - x2b * sb) * gm;
                            float o2a = (x2a * ca + x1a * sa) * gm;
                            float o2b = (x2b * cb + x1b * sb) * gm;
                            __nv_bfloat162 h1 = __floats2bfloat162_rn(o1a, o1b);
                            __nv_bfloat162 h2 = __floats2bfloat162_rn(o2a, o2b);
                            __nv_bfloat162 l1 = __floats2bfloat162_rn(
                                o1a - __bfloat162float(h1.x), o1b - __bfloat162float(h1.y));
                            __nv_bfloat162 l2 = __floats2bfloat162_rn(
                                o2a - __bfloat162float(h2.x), o2b - __bfloat162float(h2.y));
                            *(__nv_bfloat162*)(dst + i) = h1;
                            *(__nv_bfloat162*)(dst + 16 + i) = h2;
                            *(__nv_bfloat162*)(dst + 32 + i) = l1;
                            *(__nv_bfloat162*)(dst + 48 + i) = l2;
                        }
                    }
                }
            }
            return;
        }
        // ---- V half: fp32 write + transposed split via smem ----
        __syncthreads();
        float* smt = (float*)sm;            // [col 128][row 128] fp32 (64 KB of 96)
#pragma unroll
        for (int mi = 0; mi < 2; mi++) {
#pragma unroll
            for (int ni = 0; ni < 8; ni++) {
#pragma unroll
                for (int half = 0; half < 2; half++) {
                    int row = wm * 32 + mi * 16 + gq + half * 8;
                    int colL = wn * 64 + ni * 8 + tig * 2;
                    float v0 = c[mi][ni][half * 2], v1 = c[mi][ni][half * 2 + 1];
                    float2 ov = {v0, v1};
                    *(float2*)(C2 + (size_t)(bm + row) * 512 + (bn - 512) + colL) = ov;
                    smt[colL * 128 + row] = v0;
                    smt[(colL + 1) * 128 + row] = v1;
                }
            }
        }
        __syncthreads();
        int colL = tid >> 1, th = (tid & 1) * 64;
        int vcol = (bn - 512) + colL;
        int hh = vcol >> 6, d = vcol & 63;
        int bq = bm >> 11, tloc = bm & 2047;
        __nv_bfloat16* oh = g_vth + (((size_t)(bq * 8 + hh) * 64 + d) * 2048) + tloc + th;
        __nv_bfloat16* ol = g_vtl + (((size_t)(bq * 8 + hh) * 64 + d) * 2048) + tloc + th;
        const float* src = smt + colL * 128 + th;
#pragma unroll
        for (int j8 = 0; j8 < 8; j8++) {
            float4 v0 = *(const float4*)(src + j8 * 8);
            float4 v1 = *(const float4*)(src + j8 * 8 + 4);
            __nv_bfloat162 hv[4], lv[4];
            hv[0] = __floats2bfloat162_rn(v0.x, v0.y);
            hv[1] = __floats2bfloat162_rn(v0.z, v0.w);
            hv[2] = __floats2bfloat162_rn(v1.x, v1.y);
            hv[3] = __floats2bfloat162_rn(v1.z, v1.w);
            lv[0] = __floats2bfloat162_rn(v0.x - __bfloat162float(hv[0].x),
                                          v0.y - __bfloat162float(hv[0].y));
            lv[1] = __floats2bfloat162_rn(v0.z - __bfloat162float(hv[1].x),
                                          v0.w - __bfloat162float(hv[1].y));
            lv[2] = __floats2bfloat162_rn(v1.x - __bfloat162float(hv[2].x),
                                          v1.y - __bfloat162float(hv[2].y));
            lv[3] = __floats2bfloat162_rn(v1.z - __bfloat162float(hv[3].x),
                                          v1.w - __bfloat162float(hv[3].y));
            *(uint4*)(oh + j8 * 8) = *(uint4*)hv;
            *(uint4*)(ol + j8 * 8) = *(uint4*)lv;
        }
        return;
    }

    float* Cout = C;
    int bncol = bn;
#pragma unroll
    for (int mi = 0; mi < 2; mi++) {
#pragma unroll
        for (int ni = 0; ni < 8; ni++) {
#pragma unroll
            for (int half = 0; half < 2; half++) {
                int row = bm + wm * 32 + mi * 16 + gq + half * 8;
                int col = bncol + wn * 64 + ni * 8 + tig * 2;
                size_t o = (size_t)row * 512 + col;
                float v0 = c[mi][ni][half * 2], v1 = c[mi][ni][half * 2 + 1];
                if (epi == 1) {
                    float2 rr = *(const float2*)(R + o);
                    v0 += rr.x; v1 += rr.y;
                } else if (epi == 2) {
                    float2 rr = *(const float2*)(R + o);
                    v0 = rr.x + v0 / (1.0f + expf(-v0));
                    v1 = rr.y + v1 / (1.0f + expf(-v1));
                }
                if (Cout) {
                    float2 ov = {v0, v1};
                    *(float2*)(Cout + o) = ov;
                }
                if (S) {
                    __nv_bfloat16 h0 = __float2bfloat16(v0);
                    __nv_bfloat16 h1 = __float2bfloat16(v1);
                    __nv_bfloat16 l0 = __float2bfloat16(v0 - __bfloat162float(h0));
                    __nv_bfloat16 l1 = __float2bfloat16(v1 - __bfloat162float(h1));
                    size_t sbase = (size_t)row * 1024 + col;
                    __nv_bfloat162 hh; hh.x = h0; hh.y = h1;
                    __nv_bfloat162 ll; ll.x = l0; ll.y = l1;
                    *(__nv_bfloat162*)(S + sbase) = hh;
                    *(__nv_bfloat162*)(S + sbase + 512) = ll;
                }
            }
        }
    }
}

// ---------------- MMA flash attention (compact q/k, exp2 softmax) ------------
#define ATT_STG 24576
#define ATT_SMEM 49152
__global__ __launch_bounds__(128, 3) void attn_mma_kernel(__nv_bfloat16* __restrict__ Y16) {
    extern __shared__ __align__(128) char smA[];
    uint32_t sb = smem_u32(smA);

    int tid = threadIdx.x, wid = tid >> 5, lane = tid & 31;
    int gq = lane >> 2, tig = lane & 3;
    int bh = blockIdx.y, b = bh >> 3, h = bh & 7;
    int tileIdx = (int)gridDim.x - 1 - (int)blockIdx.x;  // heavy first
    int tb = tileIdx * 64;

    const __nv_bfloat16* Kg = g_ks + (size_t)bh * T_SEQ * 64;
    const __nv_bfloat16* Vhg = g_vth + (size_t)bh * 64 * T_SEQ;
    const __nv_bfloat16* Vlg = g_vtl + (size_t)bh * 64 * T_SEQ;

    {
        const __nv_bfloat16* Qg = g_qs + ((size_t)bh * T_SEQ + tb) * 64;
        int row = tid >> 1, sbase = (tid & 1) * 4;
#pragma unroll
        for (int s = 0; s < 4; s++) {
            int seg = sbase + s;
            cp16(sb + ATT_STG + (uint32_t)(row * 128 + ((seg * 16) ^ ((row & 7) << 4))),
                 Qg + (size_t)row * 64 + seg * 8);
        }
        asm volatile("cp.async.commit_group;" ::: "memory");
    }

    auto load_kv = [&](int t) {
        uint32_t st = sb + (uint32_t)(t & 1) * ATT_STG;
        int j0 = t * 64;
        int row = tid >> 1;
        int sbase = (tid & 1) * 4;
#pragma unroll
        for (int s = 0; s < 4; s++) {
            int seg = sbase + s;
            uint32_t off = (uint32_t)(row * 128 + ((seg * 16) ^ ((row & 7) << 4)));
            cp16(st + off, Kg + (size_t)(j0 + row) * 64 + seg * 8);
            cp16(st + 8192 + off, Vhg + (size_t)row * T_SEQ + j0 + seg * 8);
            cp16(st + 16384 + off, Vlg + (size_t)row * T_SEQ + j0 + seg * 8);
        }
        asm volatile("cp.async.commit_group;" ::: "memory");
    };

    load_kv(0);

    uint32_t qa[4][4];
    {
        asm volatile("cp.async.wait_group 1;" ::: "memory");
        __syncthreads();
        int qrow = wid * 16 + (lane & 15);
        uint32_t qbase = sb + ATT_STG + (uint32_t)(qrow * 128);
        uint32_t qxor = (uint32_t)((lane >> 4) << 4);
        uint32_t rxor = (uint32_t)((qrow & 7) << 4);
#pragma unroll
        for (int cidx = 0; cidx < 4; cidx++)
            ldsm4(qa[cidx][0], qa[cidx][1], qa[cidx][2], qa[cidx][3],
                  qbase + (uint32_t)(((cidx * 32) + qxor) ^ rxor));
        __syncthreads();
    }

    float o[8][4];
#pragma unroll
    for (int n = 0; n < 8; n++)
#pragma unroll
        for (int q = 0; q < 4; q++) o[n][q] = 0.f;
    float mLo = -3.0e38f, mHi = -3.0e38f, lLo = 0.f, lHi = 0.f;

    int nRow[4]; uint32_t nSw[4];
#pragma unroll
    for (int g = 0; g < 4; g++) {
        int nr = g * 16 + (lane & 7) + ((lane >> 4) << 3);
        nRow[g] = nr;
        nSw[g] = (uint32_t)(((lane & 8) << 1));
    }

    const int qi[6]   = {0, 1, 2, 3, 0, 1};
    const int koff[6] = {0, 32, 0, 32, 64, 96};

    int ntk = tileIdx + 1;
    int wminr = tb + wid * 16;

    for (int t = 0; t < ntk; t++) {
        int j0 = t * 64;
        if (t + 1 < ntk) {
            load_kv(t + 1);
            asm volatile("cp.async.wait_group 1;" ::: "memory");
        } else {
            asm volatile("cp.async.wait_group 0;" ::: "memory");
        }
        __syncthreads();
        uint32_t stage = sb + (uint32_t)(t & 1) * ATT_STG;
        uint32_t smK = stage, smVh = stage + 8192, smVl = stage + 16384;

        if (j0 <= wminr + 15) {
            float s[8][4];
#pragma unroll
            for (int n = 0; n < 8; n++)
#pragma unroll
                for (int q = 0; q < 4; q++) s[n][q] = 0.f;

#pragma unroll
            for (int kk = 0; kk < 6; kk++) {
                const uint32_t* qf = qa[qi[kk]];
#pragma unroll
                for (int g = 0; g < 4; g++) {
                    uint32_t kb[4];
                    uint32_t ka = smK + (uint32_t)(nRow[g] * 128)
                                + (uint32_t)((koff[kk] + nSw[g]) ^ ((nRow[g] & 7) << 4));
                    ldsm4(kb[0], kb[1], kb[2], kb[3], ka);
                    mma16816(s[2 * g][0], s[2 * g][1], s[2 * g][2], s[2 * g][3],
                             qf[0], qf[1], qf[2], qf[3], kb[0], kb[1]);
                    mma16816(s[2 * g + 1][0], s[2 * g + 1][1], s[2 * g + 1][2], s[2 * g + 1][3],
                             qf[0], qf[1], qf[2], qf[3], kb[2], kb[3]);
                }
            }

            int rowLo = tb + wid * 16 + gq;
            int rowHi = rowLo + 8;
            if (j0 + 63 > wminr) {
#pragma unroll
                for (int n = 0; n < 8; n++) {
                    int k0 = j0 + n * 8 + tig * 2;
                    if (k0 > rowLo)     s[n][0] = -1.0e30f;
                    if (k0 + 1 > rowLo) s[n][1] = -1.0e30f;
                    if (k0 > rowHi)     s[n][2] = -1.0e30f;
                    if (k0 + 1 > rowHi) s[n][3] = -1.0e30f;
                }
            }

            float cLo = -3.0e38f, cHi = -3.0e38f;
#pragma unroll
            for (int n = 0; n < 8; n++) {
                cLo = fmaxf(cLo, fmaxf(s[n][0], s[n][1]));
                cHi = fmaxf(cHi, fmaxf(s[n][2], s[n][3]));
            }
            cLo = fmaxf(cLo, __shfl_xor_sync(0xffffffffu, cLo, 1));
            cLo = fmaxf(cLo, __shfl_xor_sync(0xffffffffu, cLo, 2));
            cHi = fmaxf(cHi, __shfl_xor_sync(0xffffffffu, cHi, 1));
            cHi = fmaxf(cHi, __shfl_xor_sync(0xffffffffu, cHi, 2));
            float mnLo = fmaxf(mLo, cLo), mnHi = fmaxf(mHi, cHi);
            float corrLo = exp2f(mLo - mnLo), corrHi = exp2f(mHi - mnHi);
            mLo = mnLo; mHi = mnHi;
            lLo *= corrLo; lHi *= corrHi;
#pragma unroll
            for (int n = 0; n < 8; n++) {
                o[n][0] *= corrLo; o[n][1] *= corrLo;
                o[n][2] *= corrHi; o[n][3] *= corrHi;
            }

            uint32_t ph[8][2], pl[8][2];
            float psLo = 0.f, psHi = 0.f;
#pragma unroll
            for (int n = 0; n < 8; n++) {
                float p0 = exp2f(s[n][0] - mLo), p1 = exp2f(s[n][1] - mLo);
                float p2 = exp2f(s[n][2] - mHi), p3 = exp2f(s[n][3] - mHi);
                psLo += p0 + p1; psHi += p2 + p3;
                __nv_bfloat162 h01 = __floats2bfloat162_rn(p0, p1);
                __nv_bfloat162 h23 = __floats2bfloat162_rn(p2, p3);
                __nv_bfloat162 l01 = __floats2bfloat162_rn(p0 - __bfloat162float(h01.x),
                                                           p1 - __bfloat162float(h01.y));
                __nv_bfloat162 l23 = __floats2bfloat162_rn(p2 - __bfloat162float(h23.x),
                                                           p3 - __bfloat162float(h23.y));
                ph[n][0] = *(uint32_t*)&h01; ph[n][1] = *(uint32_t*)&h23;
                pl[n][0] = *(uint32_t*)&l01; pl[n][1] = *(uint32_t*)&l23;
            }
            lLo += psLo; lHi += psHi;

#pragma unroll
            for (int kk = 0; kk < 4; kk++) {
#pragma unroll
                for (int g = 0; g < 4; g++) {
                    uint32_t roff = (uint32_t)(nRow[g] * 128);
                    uint32_t xoff = (uint32_t)(((kk * 32) + nSw[g]) ^ ((nRow[g] & 7) << 4));
                    uint32_t vb[4];
                    ldsm4(vb[0], vb[1], vb[2], vb[3], smVh + roff + xoff);
                    mma16816(o[2 * g][0], o[2 * g][1], o[2 * g][2], o[2 * g][3],
                             ph[2 * kk][0], ph[2 * kk][1], ph[2 * kk + 1][0], ph[2 * kk + 1][1],
                             vb[0], vb[1]);
                    mma16816(o[2 * g + 1][0], o[2 * g + 1][1], o[2 * g + 1][2], o[2 * g + 1][3],
                             ph[2 * kk][0], ph[2 * kk][1], ph[2 * kk + 1][0], ph[2 * kk + 1][1],
                             vb[2], vb[3]);
                    mma16816(o[2 * g][0], o[2 * g][1], o[2 * g][2], o[2 * g][3],
                             pl[2 * kk][0], pl[2 * kk][1], pl[2 * kk + 1][0], pl[2 * kk + 1][1],
                             vb[0], vb[1]);
                    mma16816(o[2 * g + 1][0], o[2 * g + 1][1], o[2 * g + 1][2], o[2 * g + 1][3],
                             pl[2 * kk][0], pl[2 * kk][1], pl[2 * kk + 1][0], pl[2 * kk + 1][1],
                             vb[2], vb[3]);
                    uint32_t vc[4];
                    ldsm4(vc[0], vc[1], vc[2], vc[3], smVl + roff + xoff);
                    mma16816(o[2 * g][0], o[2 * g][1], o[2 * g][2], o[2 * g][3],
                             ph[2 * kk][0], ph[2 * kk][1], ph[2 * kk + 1][0], ph[2 * kk + 1][1],
                             vc[0], vc[1]);
                    mma16816(o[2 * g + 1][0], o[2 * g + 1][1], o[2 * g + 1][2], o[2 * g + 1][3],
                             ph[2 * kk][0], ph[2 * kk][1], ph[2 * kk + 1][0], ph[2 * kk + 1][1],
                             vc[2], vc[3]);
                }
            }
        }
        if (t + 1 < ntk) __syncthreads();
    }

    lLo += __shfl_xor_sync(0xffffffffu, lLo, 1);
    lLo += __shfl_xor_sync(0xffffffffu, lLo, 2);
    lHi += __shfl_xor_sync(0xffffffffu, lHi, 1);
    lHi += __shfl_xor_sync(0xffffffffu, lHi, 2);

#pragma unroll
    for (int hq = 0; hq < 2; hq++) {
        int row = tb + wid * 16 + gq + hq * 8;
        float linv = 1.0f / (hq ? lHi : lLo);
        int tok = b * T_SEQ + row;
        const float* vr = g_v + (size_t)tok * 512 + h * 64;
        float y0[8], y1[8];
        float2 vv[8];
        float n2 = 0.f, pr = 0.f;
#pragma unroll
        for (int n = 0; n < 8; n++) {
            vv[n] = *(const float2*)(vr + n * 8 + tig * 2);
            y0[n] = o[n][hq * 2] * linv;
            y1[n] = o[n][hq * 2 + 1] * linv;
            n2 += vv[n].x * vv[n].x + vv[n].y * vv[n].y;
            pr += y0[n] * vv[n].x + y1[n] * vv[n].y;
        }
        n2 += __shfl_xor_sync(0xffffffffu, n2, 1);
        n2 += __shfl_xor_sync(0xffffffffu, n2, 2);
        pr += __shfl_xor_sync(0xffffffffu, pr, 1);
        pr += __shfl_xor_sync(0xffffffffu, pr, 2);
        float rn = 1.0f / fmaxf(sqrtf(n2), 1e-12f);
        float prn = pr * rn * rn;
        size_t obase = (size_t)tok * 1024 + h * 64;
#pragma unroll
        for (int n = 0; n < 8; n++) {
            float a0 = y0[n] - prn * vv[n].x;
            float a1 = y1[n] - prn * vv[n].y;
            __nv_bfloat16 h0 = __float2bfloat16(a0);
            __nv_bfloat16 h1 = __float2bfloat16(a1);
            __nv_bfloat162 hh; hh.x = h0; hh.y = h1;
            __nv_bfloat162 ll;
            ll.x = __float2bfloat16(a0 - __bfloat162float(h0));
            ll.y = __float2bfloat16(a1 - __bfloat162float(h1));
            size_t p = obase + n * 8 + tig * 2;
            *(__nv_bfloat162*)(Y16 + p) = hh;
            *(__nv_bfloat162*)(Y16 + p + 512) = ll;
        }
    }
}

// ---------------- layernorm with split-bf16 output --------------------------
__global__ __launch_bounds__(256) void ln_split_kernel(const float* __restrict__ in,
                                                       const float* __restrict__ g,
                                                       const float* __restrict__ b,
                                                       __nv_bfloat16* __restrict__ S) {
    int row = blockIdx.x, tid = threadIdx.x;
    const float* rp = in + (size_t)row * 512;
    float a0 = rp[tid], a1 = rp[tid + 256];
    float s = a0 + a1, s2 = a0 * a0 + a1 * a1;
#pragma unroll
    for (int off = 16; off; off >>= 1) {
        s  += __shfl_down_sync(0xffffffffu, s, off);
        s2 += __shfl_down_sync(0xffffffffu, s2, off);
    }
    __shared__ float rs[8], rs2[8];
    __shared__ float mean_s, inv_s;
    if ((tid & 31) == 0) { rs[tid >> 5] = s; rs2[tid >> 5] = s2; }
    __syncthreads();
    if (tid == 0) {
        float S0 = 0, S2 = 0;
#pragma unroll
        for (int w = 0; w < 8; w++) { S0 += rs[w]; S2 += rs2[w]; }
        float m = S0 * (1.0f / 512.0f);
        float var = fmaxf(S2 * (1.0f / 512.0f) - m * m, 0.0f);
        mean_s = m;
        inv_s = rsqrtf(var + 1e-5f);
    }
    __syncthreads();
    float v0 = (a0 - mean_s) * inv_s * g[tid] + b[tid];
    float v1 = (a1 - mean_s) * inv_s * g[tid + 256] + b[tid + 256];
    size_t base = (size_t)row * 1024;
    __nv_bfloat16 h0 = __float2bfloat16(v0);
    __nv_bfloat16 h1 = __float2bfloat16(v1);
    S[base + tid] = h0;
    S[base + 512 + tid] = __float2bfloat16(v0 - __bfloat162float(h0));
    S[base + tid + 256] = h1;
    S[base + 512 + tid + 256] = __float2bfloat16(v1 - __bfloat162float(h1));
}

// ---------------- fused rms + final projection + tanh ------------------------
__global__ __launch_bounds__(256) void zout_rms_kernel(const float* __restrict__ he2,
                                                       const float* __restrict__ wout,
                                                       const float* __restrict__ ct,
                                                       float* __restrict__ z) {
    int token = blockIdx.x, tid = threadIdx.x;
    __shared__ float xs[512];
    __shared__ float ps[256];
    __shared__ float rs2[8];
    __shared__ float inv_s;
    const float* rp = he2 + (size_t)token * 512;
    float a0 = rp[tid], a1 = rp[tid + 256];
    xs[tid] = a0;
    xs[tid + 256] = a1;
    float s2 = a0 * a0 + a1 * a1;
#pragma unroll
    for (int off = 16; off; off >>= 1) s2 += __shfl_down_sync(0xffffffffu, s2, off);
    if ((tid & 31) == 0) rs2[tid >> 5] = s2;
    __syncthreads();
    if (tid == 0) {
        float S2 = 0;
#pragma unroll
        for (int w = 0; w < 8; w++) S2 += rs2[w];
        inv_s = rsqrtf(S2 * (1.0f / 512.0f) + 1e-6f);
    }
    __syncthreads();
    int n = tid & 31, g = tid >> 5;
    const float* wr = wout + n * 512 + g * 64;
    const float* xr = xs + g * 64;
    float p = 0.f;
#pragma unroll
    for (int d = 0; d < 64; d++) p += xr[d] * wr[d];
    ps[tid] = p;
    __syncthreads();
    if (tid < 32) {
        float s = 0.f;
#pragma unroll
        for (int gg = 0; gg < 8; gg++) s += ps[gg * 32 + tid];
        s *= inv_s;
        float c = ct[tid];
        float sp = log1pf(expf(c));
        z[(size_t)token * 32 + tid] = tanhf(s / (sp + 1e-4f));
    }
}

// ---------------- host ------------------------------------------------------
static float* sym_addr_f(const void* symbol) {
    void* p = nullptr;
    cudaGetSymbolAddress(&p, symbol);
    return (float*)p;
}
static __nv_bfloat16* sym_addr_b(const void* symbol) {
    void* p = nullptr;
    cudaGetSymbolAddress(&p, symbol);
    return (__nv_bfloat16*)p;
}

extern "C" void kernel_launch(void* const* d_in, const int* in_sizes, int n_in,
                              void* d_out, int out_size) {
    const float* x     = (const float*)d_in[0];
    const float* qp    = (const float*)d_in[1];
    const float* kp    = (const float*)d_in[2];
    const float* wv    = (const float*)d_in[3];
    const float* wproj = (const float*)d_in[4];
    const float* qgain = (const float*)d_in[5];
    const float* ew0   = (const float*)d_in[6];
    const float* g1    = (const float*)d_in[7];
    const float* b1    = (const float*)d_in[8];
    const float* ew1   = (const float*)d_in[9];
    const float* g2    = (const float*)d_in[10];
    const float* b2    = (const float*)d_in[11];
    const float* ew2   = (const float*)d_in[12];
    const float* ewout = (const float*)d_in[13];
    const float* ct    = (const float*)d_in[14];
    float* z = (float*)d_out;

    float* v     = sym_addr_f(g_v);
    float* h     = sym_addr_f(g_h);
    float* he0   = sym_addr_f(g_he0);
    float* he1   = sym_addr_f(g_he1);
    float* he2   = sym_addr_f(g_he2);

    __nv_bfloat16* a16    = sym_addr_b(g_a16);
    __nv_bfloat16* b16    = sym_addr_b(g_b16);
    __nv_bfloat16* wqkv16 = sym_addr_b(g_w16qkv);
    __nv_bfloat16* wp16   = sym_addr_b(g_w16p);
    __nv_bfloat16* we016  = sym_addr_b(g_w16e0);
    __nv_bfloat16* we116  = sym_addr_b(g_w16e1);
    __nv_bfloat16* we216  = sym_addr_b(g_w16e2);

    cudaFuncSetAttribute(gemm_mma_kernel,
                         cudaFuncAttributeMaxDynamicSharedMemorySize, GSMEM);
    cudaFuncSetAttribute(attn_mma_kernel,
                         cudaFuncAttributeMaxDynamicSharedMemorySize, ATT_SMEM);

    dim3 ggrid(4, 32);    // N=512 GEMMs
    dim3 gqkv(8, 32);     // fused N=1024 qk|v GEMM

    mega_act_kernel<<<2048, 256>>>(x);                                                 // 0
    mega_w_kernel<<<6144, 256>>>(qp, kp, wv, wproj, ew0, ew1, ew2);                    // 1
    trig_kernel<<<128, 256>>>();                                                       // 2
    gemm_mma_kernel<<<gqkv, 256, GSMEM>>>(a16, wqkv16, nullptr, nullptr, v,            // 3 <- profiled
                                          nullptr, qgain, 3);
    attn_mma_kernel<<<dim3(32, 16), 128, ATT_SMEM>>>(b16);                             // 4
    gemm_mma_kernel<<<ggrid, 256, GSMEM>>>(b16, wp16, x, h, nullptr, a16, nullptr, 1); // 5
    gemm_mma_kernel<<<ggrid, 256, GSMEM>>>(a16, we016, nullptr, he0, nullptr, nullptr, nullptr, 0); // 6
    ln_split_kernel<<<4096, 256>>>(he0, g1, b1, b16);                                  // 7
    gemm_mma_kernel<<<ggrid, 256, GSMEM>>>(b16, we116, h, he1, nullptr, nullptr, nullptr, 2);  // 8
    ln_split_kernel<<<4096, 256>>>(he1, g2, b2, a16);                                  // 9
    gemm_mma_kernel<<<ggrid, 256, GSMEM>>>(a16, we216, he1, he2, nullptr, nullptr, nullptr, 2);// 10
    zout_rms_kernel<<<4096, 256>>>(he2, ewout, ct, z);                                 // 11
}

// round 13
// speedup vs baseline: 1.7493x; 1.7493x over previous
#include <cuda_runtime.h>
#include <cuda_bf16.h>
#include <math.h>
#include <stdint.h>

#define T_SEQ 2048
#define NTOK  4096
#define DM    512
#define NH    8
#define DH    64
#define DP    32

typedef unsigned long long ull;

// ---------------- mma / async helpers ----------------------------------------
__device__ __forceinline__ uint32_t smem_u32(const void* p) {
    uint32_t a;
    asm("{ .reg .u64 t; cvta.to.shared.u64 t, %1; cvt.u32.u64 %0, t; }"
        : "=r"(a) : "l"(p));
    return a;
}
__device__ __forceinline__ void cp16(uint32_t dst, const void* src) {
    asm volatile("cp.async.cg.shared.global [%0], [%1], 16;"
        :: "r"(dst), "l"(src) : "memory");
}
__device__ __forceinline__ void ldsm4(uint32_t& r0, uint32_t& r1, uint32_t& r2,
                                      uint32_t& r3, uint32_t addr) {
    asm volatile("ldmatrix.sync.aligned.m8n8.x4.shared.b16 {%0,%1,%2,%3}, [%4];"
        : "=r"(r0), "=r"(r1), "=r"(r2), "=r"(r3) : "r"(addr));
}
__device__ __forceinline__ void mma16816(float& c0, float& c1, float& c2, float& c3,
                                         uint32_t a0, uint32_t a1, uint32_t a2,
                                         uint32_t a3, uint32_t b0, uint32_t b1) {
    asm volatile("mma.sync.aligned.m16n8k16.row.col.f32.bf16.bf16.f32 "
        "{%0,%1,%2,%3}, {%4,%5,%6,%7}, {%8,%9}, {%0,%1,%2,%3};"
        : "+f"(c0), "+f"(c1), "+f"(c2), "+f"(c3)
        : "r"(a0), "r"(a1), "r"(a2), "r"(a3), "r"(b0), "r"(b1));
}

// ---------------- scratch (device globals) ----------------------------------
__device__ __align__(16) float g_qkraw[NTOK * 512];
__device__ __align__(16) float g_v[NTOK * DM];
__device__ __align__(16) float g_h[NTOK * DM];
__device__ __align__(16) float g_he0[NTOK * DM];
__device__ __align__(16) float g_he1[NTOK * DM];
__device__ __align__(16) float g_he2[NTOK * DM];
__device__ __align__(16) float g_cos[T_SEQ * 16];
__device__ __align__(16) float g_sin[T_SEQ * 16];

// q/k bf16 split (compact): [bh][t][64]; q = [qh|ql] (log2e folded), k = [kh|kl]
__device__ __align__(16) __nv_bfloat16 g_qs[16 * T_SEQ * 64];
__device__ __align__(16) __nv_bfloat16 g_ks[16 * T_SEQ * 64];
// transposed V splits: [bh][dim 64][t 2048]
__device__ __align__(16) __nv_bfloat16 g_vth[16 * 64 * T_SEQ];
__device__ __align__(16) __nv_bfloat16 g_vtl[16 * 64 * T_SEQ];

// activation split buffers (compact [hi|lo], 1024 cols)
__device__ __align__(16) __nv_bfloat16 g_a16[NTOK * 1024];
__device__ __align__(16) __nv_bfloat16 g_b16[NTOK * 1024];
// weight split buffers (compact [hi|lo])
__device__ __align__(16) __nv_bfloat16 g_w16qkv[1024 * 1024];  // rows 0-511 qk, 512-1023 v
__device__ __align__(16) __nv_bfloat16 g_w16p[512 * 1024];
__device__ __align__(16) __nv_bfloat16 g_w16e0[512 * 1024];
__device__ __align__(16) __nv_bfloat16 g_w16e1[512 * 1024];
__device__ __align__(16) __nv_bfloat16 g_w16e2[512 * 1024];

// ---------------- activation split of x (vectorized) -------------------------
__global__ __launch_bounds__(256) void mega_act_kernel(const float* __restrict__ x) {
    int idx4 = blockIdx.x * 256 + threadIdx.x;
    int row = idx4 >> 7, c = (idx4 & 127) * 4;
    float4 v = *(const float4*)(x + (size_t)row * 512 + c);
    size_t base = (size_t)row * 1024 + c;
    __nv_bfloat162 h01 = __floats2bfloat162_rn(v.x, v.y);
    __nv_bfloat162 h23 = __floats2bfloat162_rn(v.z, v.w);
    __nv_bfloat162 l01 = __floats2bfloat162_rn(v.x - __bfloat162float(h01.x),
                                               v.y - __bfloat162float(h01.y));
    __nv_bfloat162 l23 = __floats2bfloat162_rn(v.z - __bfloat162float(h23.x),
                                               v.w - __bfloat162float(h23.y));
    *(__nv_bfloat162*)(g_a16 + base) = h01;
    *(__nv_bfloat162*)(g_a16 + base + 2) = h23;
    *(__nv_bfloat162*)(g_a16 + base + 512) = l01;
    *(__nv_bfloat162*)(g_a16 + base + 514) = l23;
}

// ---------------- weight splits + trig table ---------------------------------
// blocks: [0,2048) wqkv, [2048,3072) wp, [3072,4096) we0, [4096,5120) we1,
//         [5120,6144) we2, [6144,6272) trig
__global__ __launch_bounds__(256) void mega_w_kernel(
    const float* __restrict__ qp, const float* __restrict__ kp,
    const float* __restrict__ wv, const float* __restrict__ wproj,
    const float* __restrict__ ew0, const float* __restrict__ ew1,
    const float* __restrict__ ew2)
{
    int blk = blockIdx.x, tid = threadIdx.x;
    if (blk < 2048) {
        int idx = blk * 256 + tid;
        int row = idx >> 9, col = idx & 511;
        float v;
        if (row < 512) {
            const float* s = (row < 256) ? qp : kp;
            int nn = row & 255;
            int hh = nn >> 5, o = nn & 31;
            v = s[hh * 16384 + col * 32 + o];
        } else {
            v = wv[(size_t)(row - 512) * 512 + col];
        }
        __nv_bfloat16 h = __float2bfloat16(v);
        size_t base = (size_t)row * 1024;
        g_w16qkv[base + col] = h;
        g_w16qkv[base + 512 + col] = __float2bfloat16(v - __bfloat162float(h));
        return;
    }
    if (blk < 6144) {
        const float* src; __nv_bfloat16* dst;
        int idx;
        if (blk < 3072)      { src = wproj; dst = g_w16p;  idx = (blk - 2048) * 256 + tid; }
        else if (blk < 4096) { src = ew0;   dst = g_w16e0; idx = (blk - 3072) * 256 + tid; }
        else if (blk < 5120) { src = ew1;   dst = g_w16e1; idx = (blk - 4096) * 256 + tid; }
        else                 { src = ew2;   dst = g_w16e2; idx = (blk - 5120) * 256 + tid; }
        int row = idx >> 9, col = idx & 511;
        float v = src[idx];
        __nv_bfloat16 h = __float2bfloat16(v);
        size_t base = (size_t)row * 1024;
        dst[base + col] = h;
        dst[base + 512 + col] = __float2bfloat16(v - __bfloat162float(h));
        return;
    }
    {
        int idx = (blk - 6144) * 256 + tid;
        if (idx >= T_SEQ * 16) return;
        int t = idx >> 4, i = idx & 15;
        double p = pow(10000.0, (double)i / 16.0);
        float pf = (float)p;
        float freq = 1.0f / pf;
        float ang = (float)t * freq;
        g_cos[idx] = (float)cos((double)ang);
        g_sin[idx] = (float)sin((double)ang);
    }
}

// ---------------- HMMA GEMM (128x128 tile, 2-stage cp.async) -----------------
// epi: 0 none, 1 C=R+acc, 2 C=R+silu(acc), 3 qkv mode (bn<512 -> C fp32;
//      bn>=512 -> C2 fp32 + transposed split to g_vth/g_vtl via smem).
#define NKT 24
#define STG 32768
#define GSMEM (2 * STG)
__global__ __launch_bounds__(256) void gemm_mma_kernel(
    const __nv_bfloat16* __restrict__ A16, const __nv_bfloat16* __restrict__ W16,
    const float* __restrict__ R, float* __restrict__ C, float* __restrict__ C2,
    __nv_bfloat16* __restrict__ S, int epi)
{
    extern __shared__ __align__(128) char sm[];
    uint32_t sb = smem_u32(sm);

    int tid = threadIdx.x, wid = tid >> 5, lane = tid & 31;
    int bm = blockIdx.y * 128, bn = blockIdx.x * 128;
    int wm = wid >> 1, wn = wid & 1;

    const __nv_bfloat16* Abase = A16 + (size_t)bm * 1024;
    const __nv_bfloat16* Wbase = W16 + (size_t)bn * 1024;

    auto load_stage = [&](int kt) {
        uint32_t dA = sb + (uint32_t)(kt & 1) * STG;
        uint32_t dB = dA + 16384;
        int aOff = ((kt < 16) ? kt : kt - 16) * 64;
        int wOff = ((kt < 8) ? kt : kt - 8) * 64;
#pragma unroll
        for (int it = 0; it < 4; it++) {
            int idx = it * 256 + tid, row = idx >> 3, seg = idx & 7;
            uint32_t off = (uint32_t)(row * 128 + ((seg * 16) ^ ((row & 7) << 4)));
            cp16(dA + off, Abase + (size_t)row * 1024 + aOff + seg * 8);
        }
#pragma unroll
        for (int it = 0; it < 4; it++) {
            int idx = it * 256 + tid, row = idx >> 3, seg = idx & 7;
            uint32_t off = (uint32_t)(row * 128 + ((seg * 16) ^ ((row & 7) << 4)));
            cp16(dB + off, Wbase + (size_t)row * 1024 + wOff + seg * 8);
        }
        asm volatile("cp.async.commit_group;" ::: "memory");
    };

    int aRow[2]; uint32_t aSw[2];
#pragma unroll
    for (int mi = 0; mi < 2; mi++) {
        int row = wm * 32 + mi * 16 + (lane & 15);
        aRow[mi] = row;
        aSw[mi] = (uint32_t)((((lane >> 4) << 4)) ^ ((row & 7) << 4));
    }
    int bRow[4]; uint32_t bSw[4];
#pragma unroll
    for (int g = 0; g < 4; g++) {
        int nrow = wn * 64 + g * 16 + (lane & 7) + ((lane >> 4) << 3);
        bRow[g] = nrow;
        bSw[g] = (uint32_t)(((lane & 8) << 1) ^ ((nrow & 7) << 4));
    }

    float c[2][8][4];
#pragma unroll
    for (int mi = 0; mi < 2; mi++)
#pragma unroll
        for (int ni = 0; ni < 8; ni++)
#pragma unroll
            for (int q = 0; q < 4; q++) c[mi][ni][q] = 0.f;

    load_stage(0);

    for (int kt = 0; kt < NKT; kt++) {
        if (kt + 1 < NKT) {
            load_stage(kt + 1);
            asm volatile("cp.async.wait_group 1;" ::: "memory");
        } else {
            asm volatile("cp.async.wait_group 0;" ::: "memory");
        }
        __syncthreads();
        uint32_t base = sb + (uint32_t)(kt & 1) * STG;
        uint32_t baseB = base + 16384;
#pragma unroll
        for (int ks = 0; ks < 4; ks++) {
            uint32_t a0[4], a1[4], b[4][4];
            ldsm4(a0[0], a0[1], a0[2], a0[3],
                  base + (uint32_t)(aRow[0] * 128) + (uint32_t)((ks * 32) ^ aSw[0]));
            ldsm4(a1[0], a1[1], a1[2], a1[3],
                  base + (uint32_t)(aRow[1] * 128) + (uint32_t)((ks * 32) ^ aSw[1]));
#pragma unroll
            for (int g = 0; g < 4; g++)
                ldsm4(b[g][0], b[g][1], b[g][2], b[g][3],
                      baseB + (uint32_t)(bRow[g] * 128) + (uint32_t)((ks * 32) ^ bSw[g]));
#pragma unroll
            for (int g = 0; g < 4; g++) {
                mma16816(c[0][2 * g][0], c[0][2 * g][1], c[0][2 * g][2], c[0][2 * g][3],
                         a0[0], a0[1], a0[2], a0[3], b[g][0], b[g][1]);
                mma16816(c[0][2 * g + 1][0], c[0][2 * g + 1][1], c[0][2 * g + 1][2], c[0][2 * g + 1][3],
                         a0[0], a0[1], a0[2], a0[3], b[g][2], b[g][3]);
                mma16816(c[1][2 * g][0], c[1][2 * g][1], c[1][2 * g][2], c[1][2 * g][3],
                         a1[0], a1[1], a1[2], a1[3], b[g][0], b[g][1]);
                mma16816(c[1][2 * g + 1][0], c[1][2 * g + 1][1], c[1][2 * g + 1][2], c[1][2 * g + 1][3],
                         a1[0], a1[1], a1[2], a1[3], b[g][2], b[g][3]);
            }
        }
        if (kt + 1 < NKT) __syncthreads();
    }

    int gq = lane >> 2, tig = lane & 3;

    if (epi == 3 && bn >= 512) {
        // ---- V half: fp32 write + transposed split via smem ----
        __syncthreads();
        float* smt = (float*)sm;            // [col 128][row 128] fp32
#pragma unroll
        for (int mi = 0; mi < 2; mi++) {
#pragma unroll
            for (int ni = 0; ni < 8; ni++) {
#pragma unroll
                for (int half = 0; half < 2; half++) {
                    int row = wm * 32 + mi * 16 + gq + half * 8;
                    int colL = wn * 64 + ni * 8 + tig * 2;
                    float v0 = c[mi][ni][half * 2], v1 = c[mi][ni][half * 2 + 1];
                    float2 ov = {v0, v1};
                    *(float2*)(C2 + (size_t)(bm + row) * 512 + (bn - 512) + colL) = ov;
                    smt[colL * 128 + row] = v0;
                    smt[(colL + 1) * 128 + row] = v1;
                }
            }
        }
        __syncthreads();
        int colL = tid >> 1, th = (tid & 1) * 64;
        int vcol = (bn - 512) + colL;
        int hh = vcol >> 6, d = vcol & 63;
        int bq = bm >> 11, tloc = bm & 2047;
        __nv_bfloat16* oh = g_vth + (((size_t)(bq * 8 + hh) * 64 + d) * 2048) + tloc + th;
        __nv_bfloat16* ol = g_vtl + (((size_t)(bq * 8 + hh) * 64 + d) * 2048) + tloc + th;
        const float* src = smt + colL * 128 + th;
#pragma unroll
        for (int j8 = 0; j8 < 8; j8++) {
            float4 v0 = *(const float4*)(src + j8 * 8);
            float4 v1 = *(const float4*)(src + j8 * 8 + 4);
            __nv_bfloat162 hv[4], lv[4];
            hv[0] = __floats2bfloat162_rn(v0.x, v0.y);
            hv[1] = __floats2bfloat162_rn(v0.z, v0.w);
            hv[2] = __floats2bfloat162_rn(v1.x, v1.y);
            hv[3] = __floats2bfloat162_rn(v1.z, v1.w);
            lv[0] = __floats2bfloat162_rn(v0.x - __bfloat162float(hv[0].x),
                                          v0.y - __bfloat162float(hv[0].y));
            lv[1] = __floats2bfloat162_rn(v0.z - __bfloat162float(hv[1].x),
                                          v0.w - __bfloat162float(hv[1].y));
            lv[2] = __floats2bfloat162_rn(v1.x - __bfloat162float(hv[2].x),
                                          v1.y - __bfloat162float(hv[2].y));
            lv[3] = __floats2bfloat162_rn(v1.z - __bfloat162float(hv[3].x),
                                          v1.w - __bfloat162float(hv[3].y));
            *(uint4*)(oh + j8 * 8) = *(uint4*)hv;
            *(uint4*)(ol + j8 * 8) = *(uint4*)lv;
        }
        return;
    }

    float* Cout = C;
    int bncol = bn;
#pragma unroll
    for (int mi = 0; mi < 2; mi++) {
#pragma unroll
        for (int ni = 0; ni < 8; ni++) {
#pragma unroll
            for (int half = 0; half < 2; half++) {
                int row = bm + wm * 32 + mi * 16 + gq + half * 8;
                int col = bncol + wn * 64 + ni * 8 + tig * 2;
                size_t o = (size_t)row * 512 + col;
                float v0 = c[mi][ni][half * 2], v1 = c[mi][ni][half * 2 + 1];
                if (epi == 1) {
                    float2 rr = *(const float2*)(R + o);
                    v0 += rr.x; v1 += rr.y;
                } else if (epi == 2) {
                    float2 rr = *(const float2*)(R + o);
                    v0 = rr.x + v0 / (1.0f + expf(-v0));
                    v1 = rr.y + v1 / (1.0f + expf(-v1));
                }
                if (Cout) {
                    float2 ov = {v0, v1};
                    *(float2*)(Cout + o) = ov;
                }
                if (S) {
                    __nv_bfloat16 h0 = __float2bfloat16(v0);
                    __nv_bfloat16 h1 = __float2bfloat16(v1);
                    __nv_bfloat16 l0 = __float2bfloat16(v0 - __bfloat162float(h0));
                    __nv_bfloat16 l1 = __float2bfloat16(v1 - __bfloat162float(h1));
                    size_t sbase = (size_t)row * 1024 + col;
                    __nv_bfloat162 hh; hh.x = h0; hh.y = h1;
                    __nv_bfloat162 ll; ll.x = l0; ll.y = l1;
                    *(__nv_bfloat162*)(S + sbase) = hh;
                    *(__nv_bfloat162*)(S + sbase + 512) = ll;
                }
            }
        }
    }
}

// ---------------- RoPE (log2e folded into q) ---------------------------------
__global__ __launch_bounds__(256) void rope_kernel(const float* __restrict__ qkraw,
                                                   const float* __restrict__ gain) {
    int token = blockIdx.x;
    int b = token >> 11, t = token & 2047;
    int tid = threadIdx.x;
    int h = tid >> 5, o = tid & 31, i = o & 15;
    float c = g_cos[t * 16 + i];
    float s = g_sin[t * 16 + i];
    const float* row = qkraw + (size_t)token * 512;

    float q1 = row[h * 32 + i], q2 = row[h * 32 + i + 16];
    float qv = (o < 16) ? (q1 * c - q2 * s) : (q2 * c + q1 * s);
    qv *= gain[h] * 0.17677669529663687f * 1.4426950408889634f;  // /sqrt(32) * log2e

    float k1 = row[256 + h * 32 + i], k2 = row[256 + h * 32 + i + 16];
    float kv = (o < 16) ? (k1 * c - k2 * s) : (k2 * c + k1 * s);

    size_t base = ((size_t)(b * 8 + h) * T_SEQ + t) * 64;
    __nv_bfloat16 qh = __float2bfloat16(qv);
    g_qs[base + o] = qh;
    g_qs[base + 32 + o] = __float2bfloat16(qv - __bfloat162float(qh));

    __nv_bfloat16 kh = __float2bfloat16(kv);
    g_ks[base + o] = kh;
    g_ks[base + 32 + o] = __float2bfloat16(kv - __bfloat162float(kh));
}

// ---------------- MMA flash attention (compact q/k, exp2 softmax) ------------
#define ATT_STG 24576
#define ATT_SMEM 49152
__global__ __launch_bounds__(128, 3) void attn_mma_kernel(__nv_bfloat16* __restrict__ Y16) {
    extern __shared__ __align__(128) char smA[];
    uint32_t sb = smem_u32(smA);

    int tid = threadIdx.x, wid = tid >> 5, lane = tid & 31;
    int gq = lane >> 2, tig = lane & 3;
    int bh = blockIdx.y, b = bh >> 3, h = bh & 7;
    int tileIdx = (int)gridDim.x - 1 - (int)blockIdx.x;  // heavy first
    int tb = tileIdx * 64;

    const __nv_bfloat16* Kg = g_ks + (size_t)bh * T_SEQ * 64;
    const __nv_bfloat16* Vhg = g_vth + (size_t)bh * 64 * T_SEQ;
    const __nv_bfloat16* Vlg = g_vtl + (size_t)bh * 64 * T_SEQ;

    {
        const __nv_bfloat16* Qg = g_qs + ((size_t)bh * T_SEQ + tb) * 64;
        int row = tid >> 1, sbase = (tid & 1) * 4;
#pragma unroll
        for (int s = 0; s < 4; s++) {
            int seg = sbase + s;
            cp16(sb + ATT_STG + (uint32_t)(row * 128 + ((seg * 16) ^ ((row & 7) << 4))),
                 Qg + (size_t)row * 64 + seg * 8);
        }
        asm volatile("cp.async.commit_group;" ::: "memory");
    }

    auto load_kv = [&](int t) {
        uint32_t st = sb + (uint32_t)(t & 1) * ATT_STG;
        int j0 = t * 64;
        int row = tid >> 1;
        int sbase = (tid & 1) * 4;
#pragma unroll
        for (int s = 0; s < 4; s++) {
            int seg = sbase + s;
            uint32_t off = (uint32_t)(row * 128 + ((seg * 16) ^ ((row & 7) << 4)));
            cp16(st + off, Kg + (size_t)(j0 + row) * 64 + seg * 8);
            cp16(st + 8192 + off, Vhg + (size_t)row * T_SEQ + j0 + seg * 8);
            cp16(st + 16384 + off, Vlg + (size_t)row * T_SEQ + j0 + seg * 8);
        }
        asm volatile("cp.async.commit_group;" ::: "memory");
    };

    load_kv(0);

    uint32_t qa[4][4];
    {
        asm volatile("cp.async.wait_group 1;" ::: "memory");
        __syncthreads();
        int qrow = wid * 16 + (lane & 15);
        uint32_t qbase = sb + ATT_STG + (uint32_t)(qrow * 128);
        uint32_t qxor = (uint32_t)((lane >> 4) << 4);
        uint32_t rxor = (uint32_t)((qrow & 7) << 4);
#pragma unroll
        for (int cidx = 0; cidx < 4; cidx++)
            ldsm4(qa[cidx][0], qa[cidx][1], qa[cidx][2], qa[cidx][3],
                  qbase + (uint32_t)(((cidx * 32) + qxor) ^ rxor));
        __syncthreads();
    }

    float o[8][4];
#pragma unroll
    for (int n = 0; n < 8; n++)
#pragma unroll
        for (int q = 0; q < 4; q++) o[n][q] = 0.f;
    float mLo = -3.0e38f, mHi = -3.0e38f, lLo = 0.f, lHi = 0.f;

    int nRow[4]; uint32_t nSw[4];
#pragma unroll
    for (int g = 0; g < 4; g++) {
        int nr = g * 16 + (lane & 7) + ((lane >> 4) << 3);
        nRow[g] = nr;
        nSw[g] = (uint32_t)(((lane & 8) << 1));
    }

    const int qi[6]   = {0, 1, 2, 3, 0, 1};
    const int koff[6] = {0, 32, 0, 32, 64, 96};

    int ntk = tileIdx + 1;
    int wminr = tb + wid * 16;

    for (int t = 0; t < ntk; t++) {
        int j0 = t * 64;
        if (t + 1 < ntk) {
            load_kv(t + 1);
            asm volatile("cp.async.wait_group 1;" ::: "memory");
        } else {
            asm volatile("cp.async.wait_group 0;" ::: "memory");
        }
        __syncthreads();
        uint32_t stage = sb + (uint32_t)(t & 1) * ATT_STG;
        uint32_t smK = stage, smVh = stage + 8192, smVl = stage + 16384;

        if (j0 <= wminr + 15) {
            float s[8][4];
#pragma unroll
            for (int n = 0; n < 8; n++)
#pragma unroll
                for (int q = 0; q < 4; q++) s[n][q] = 0.f;

#pragma unroll
            for (int kk = 0; kk < 6; kk++) {
                const uint32_t* qf = qa[qi[kk]];
#pragma unroll
                for (int g = 0; g < 4; g++) {
                    uint32_t kb[4];
                    uint32_t ka = smK + (uint32_t)(nRow[g] * 128)
                                + (uint32_t)((koff[kk] + nSw[g]) ^ ((nRow[g] & 7) << 4));
                    ldsm4(kb[0], kb[1], kb[2], kb[3], ka);
                    mma16816(s[2 * g][0], s[2 * g][1], s[2 * g][2], s[2 * g][3],
                             qf[0], qf[1], qf[2], qf[3], kb[0], kb[1]);
                    mma16816(s[2 * g + 1][0], s[2 * g + 1][1], s[2 * g + 1][2], s[2 * g + 1][3],
                             qf[0], qf[1], qf[2], qf[3], kb[2], kb[3]);
                }
            }

            int rowLo = tb + wid * 16 + gq;
            int rowHi = rowLo + 8;
            if (j0 + 63 > wminr) {
#pragma unroll
                for (int n = 0; n < 8; n++) {
                    int k0 = j0 + n * 8 + tig * 2;
                    if (k0 > rowLo)     s[n][0] = -1.0e30f;
                    if (k0 + 1 > rowLo) s[n][1] = -1.0e30f;
                    if (k0 > rowHi)     s[n][2] = -1.0e30f;
                    if (k0 + 1 > rowHi) s[n][3] = -1.0e30f;
                }
            }

            float cLo = -3.0e38f, cHi = -3.0e38f;
#pragma unroll
            for (int n = 0; n < 8; n++) {
                cLo = fmaxf(cLo, fmaxf(s[n][0], s[n][1]));
                cHi = fmaxf(cHi, fmaxf(s[n][2], s[n][3]));
            }
            cLo = fmaxf(cLo, __shfl_xor_sync(0xffffffffu, cLo, 1));
            cLo = fmaxf(cLo, __shfl_xor_sync(0xffffffffu, cLo, 2));
            cHi = fmaxf(cHi, __shfl_xor_sync(0xffffffffu, cHi, 1));
            cHi = fmaxf(cHi, __shfl_xor_sync(0xffffffffu, cHi, 2));
            float mnLo = fmaxf(mLo, cLo), mnHi = fmaxf(mHi, cHi);
            float corrLo = exp2f(mLo - mnLo), corrHi = exp2f(mHi - mnHi);
            mLo = mnLo; mHi = mnHi;
            lLo *= corrLo; lHi *= corrHi;
#pragma unroll
            for (int n = 0; n < 8; n++) {
                o[n][0] *= corrLo; o[n][1] *= corrLo;
                o[n][2] *= corrHi; o[n][3] *= corrHi;
            }

            uint32_t ph[8][2], pl[8][2];
            float psLo = 0.f, psHi = 0.f;
#pragma unroll
            for (int n = 0; n < 8; n++) {
                float p0 = exp2f(s[n][0] - mLo), p1 = exp2f(s[n][1] - mLo);
                float p2 = exp2f(s[n][2] - mHi), p3 = exp2f(s[n][3] - mHi);
                psLo += p0 + p1; psHi += p2 + p3;
                __nv_bfloat162 h01 = __floats2bfloat162_rn(p0, p1);
                __nv_bfloat162 h23 = __floats2bfloat162_rn(p2, p3);
                __nv_bfloat162 l01 = __floats2bfloat162_rn(p0 - __bfloat162float(h01.x),
                                                           p1 - __bfloat162float(h01.y));
                __nv_bfloat162 l23 = __floats2bfloat162_rn(p2 - __bfloat162float(h23.x),
                                                           p3 - __bfloat162float(h23.y));
                ph[n][0] = *(uint32_t*)&h01; ph[n][1] = *(uint32_t*)&h23;
                pl[n][0] = *(uint32_t*)&l01; pl[n][1] = *(uint32_t*)&l23;
            }
            lLo += psLo; lHi += psHi;

#pragma unroll
            for (int kk = 0; kk < 4; kk++) {
#pragma unroll
                for (int g = 0; g < 4; g++) {
                    uint32_t roff = (uint32_t)(nRow[g] * 128);
                    uint32_t xoff = (uint32_t)(((kk * 32) + nSw[g]) ^ ((nRow[g] & 7) << 4));
                    uint32_t vb[4];
                    ldsm4(vb[0], vb[1], vb[2], vb[3], smVh + roff + xoff);
                    mma16816(o[2 * g][0], o[2 * g][1], o[2 * g][2], o[2 * g][3],
                             ph[2 * kk][0], ph[2 * kk][1], ph[2 * kk + 1][0], ph[2 * kk + 1][1],
                             vb[0], vb[1]);
                    mma16816(o[2 * g + 1][0], o[2 * g + 1][1], o[2 * g + 1][2], o[2 * g + 1][3],
                             ph[2 * kk][0], ph[2 * kk][1], ph[2 * kk + 1][0], ph[2 * kk + 1][1],
                             vb[2], vb[3]);
                    mma16816(o[2 * g][0], o[2 * g][1], o[2 * g][2], o[2 * g][3],
                             pl[2 * kk][0], pl[2 * kk][1], pl[2 * kk + 1][0], pl[2 * kk + 1][1],
                             vb[0], vb[1]);
                    mma16816(o[2 * g + 1][0], o[2 * g + 1][1], o[2 * g + 1][2], o[2 * g + 1][3],
                             pl[2 * kk][0], pl[2 * kk][1], pl[2 * kk + 1][0], pl[2 * kk + 1][1],
                             vb[2], vb[3]);
                    uint32_t vc[4];
                    ldsm4(vc[0], vc[1], vc[2], vc[3], smVl + roff + xoff);
                    mma16816(o[2 * g][0], o[2 * g][1], o[2 * g][2], o[2 * g][3],
                             ph[2 * kk][0], ph[2 * kk][1], ph[2 * kk + 1][0], ph[2 * kk + 1][1],
                             vc[0], vc[1]);
                    mma16816(o[2 * g + 1][0], o[2 * g + 1][1], o[2 * g + 1][2], o[2 * g + 1][3],
                             ph[2 * kk][0], ph[2 * kk][1], ph[2 * kk + 1][0], ph[2 * kk + 1][1],
                             vc[2], vc[3]);
                }
            }
        }
        if (t + 1 < ntk) __syncthreads();
    }

    lLo += __shfl_xor_sync(0xffffffffu, lLo, 1);
    lLo += __shfl_xor_sync(0xffffffffu, lLo, 2);
    lHi += __shfl_xor_sync(0xffffffffu, lHi, 1);
    lHi += __shfl_xor_sync(0xffffffffu, lHi, 2);

#pragma unroll
    for (int hq = 0; hq < 2; hq++) {
        int row = tb + wid * 16 + gq + hq * 8;
        float linv = 1.0f / (hq ? lHi : lLo);
        int tok = b * T_SEQ + row;
        const float* vr = g_v + (size_t)tok * 512 + h * 64;
        float y0[8], y1[8];
        float2 vv[8];
        float n2 = 0.f, pr = 0.f;
#pragma unroll
        for (int n = 0; n < 8; n++) {
            vv[n] = *(const float2*)(vr + n * 8 + tig * 2);
            y0[n] = o[n][hq * 2] * linv;
            y1[n] = o[n][hq * 2 + 1] * linv;
            n2 += vv[n].x * vv[n].x + vv[n].y * vv[n].y;
            pr += y0[n] * vv[n].x + y1[n] * vv[n].y;
        }
        n2 += __shfl_xor_sync(0xffffffffu, n2, 1);
        n2 += __shfl_xor_sync(0xffffffffu, n2, 2);
        pr += __shfl_xor_sync(0xffffffffu, pr, 1);
        pr += __shfl_xor_sync(0xffffffffu, pr, 2);
        float rn = 1.0f / fmaxf(sqrtf(n2), 1e-12f);
        float prn = pr * rn * rn;
        size_t obase = (size_t)tok * 1024 + h * 64;
#pragma unroll
        for (int n = 0; n < 8; n++) {
            float a0 = y0[n] - prn * vv[n].x;
            float a1 = y1[n] - prn * vv[n].y;
            __nv_bfloat16 h0 = __float2bfloat16(a0);
            __nv_bfloat16 h1 = __float2bfloat16(a1);
            __nv_bfloat162 hh; hh.x = h0; hh.y = h1;
            __nv_bfloat162 ll;
            ll.x = __float2bfloat16(a0 - __bfloat162float(h0));
            ll.y = __float2bfloat16(a1 - __bfloat162float(h1));
            size_t p = obase + n * 8 + tig * 2;
            *(__nv_bfloat162*)(Y16 + p) = hh;
            *(__nv_bfloat162*)(Y16 + p + 512) = ll;
        }
    }
}

// ---------------- layernorm with split-bf16 output --------------------------
__global__ __launch_bounds__(256) void ln_split_kernel(const float* __restrict__ in,
                                                       const float* __restrict__ g,
                                                       const float* __restrict__ b,
                                                       __nv_bfloat16* __restrict__ S) {
    int row = blockIdx.x, tid = threadIdx.x;
    const float* rp = in + (size_t)row * 512;
    float a0 = rp[tid], a1 = rp[tid + 256];
    float s = a0 + a1, s2 = a0 * a0 + a1 * a1;
#pragma unroll
    for (int off = 16; off; off >>= 1) {
        s  += __shfl_down_sync(0xffffffffu, s, off);
        s2 += __shfl_down_sync(0xffffffffu, s2, off);
    }
    __shared__ float rs[8], rs2[8];
    __shared__ float mean_s, inv_s;
    if ((tid & 31) == 0) { rs[tid >> 5] = s; rs2[tid >> 5] = s2; }
    __syncthreads();
    if (tid == 0) {
        float S0 = 0, S2 = 0;
#pragma unroll
        for (int w = 0; w < 8; w++) { S0 += rs[w]; S2 += rs2[w]; }
        float m = S0 * (1.0f / 512.0f);
        float var = fmaxf(S2 * (1.0f / 512.0f) - m * m, 0.0f);
        mean_s = m;
        inv_s = rsqrtf(var + 1e-5f);
    }
    __syncthreads();
    float v0 = (a0 - mean_s) * inv_s * g[tid] + b[tid];
    float v1 = (a1 - mean_s) * inv_s * g[tid + 256] + b[tid + 256];
    size_t base = (size_t)row * 1024;
    __nv_bfloat16 h0 = __float2bfloat16(v0);
    __nv_bfloat16 h1 = __float2bfloat16(v1);
    S[base + tid] = h0;
    S[base + 512 + tid] = __float2bfloat16(v0 - __bfloat162float(h0));
    S[base + tid + 256] = h1;
    S[base + 512 + tid + 256] = __float2bfloat16(v1 - __bfloat162float(h1));
}

// ---------------- fused rms + final projection + tanh ------------------------
__global__ __launch_bounds__(256) void zout_rms_kernel(const float* __restrict__ he2,
                                                       const float* __restrict__ wout,
                                                       const float* __restrict__ ct,
                                                       float* __restrict__ z) {
    int token = blockIdx.x, tid = threadIdx.x;
    __shared__ float xs[512];
    __shared__ float ps[256];
    __shared__ float rs2[8];
    __shared__ float inv_s;
    const float* rp = he2 + (size_t)token * 512;
    float a0 = rp[tid], a1 = rp[tid + 256];
    xs[tid] = a0;
    xs[tid + 256] = a1;
    float s2 = a0 * a0 + a1 * a1;
#pragma unroll
    for (int off = 16; off; off >>= 1) s2 += __shfl_down_sync(0xffffffffu, s2, off);
    if ((tid & 31) == 0) rs2[tid >> 5] = s2;
    __syncthreads();
    if (tid == 0) {
        float S2 = 0;
#pragma unroll
        for (int w = 0; w < 8; w++) S2 += rs2[w];
        inv_s = rsqrtf(S2 * (1.0f / 512.0f) + 1e-6f);
    }
    __syncthreads();
    int n = tid & 31, g = tid >> 5;
    const float* wr = wout + n * 512 + g * 64;
    const float* xr = xs + g * 64;
    float p = 0.f;
#pragma unroll
    for (int d = 0; d < 64; d++) p += xr[d] * wr[d];
    ps[tid] = p;
    __syncthreads();
    if (tid < 32) {
        float s = 0.f;
#pragma unroll
        for (int gg = 0; gg < 8; gg++) s += ps[gg * 32 + tid];
        s *= inv_s;
        float c = ct[tid];
        float sp = log1pf(expf(c));
        z[(size_t)token * 32 + tid] = tanhf(s / (sp + 1e-4f));
    }
}

// ---------------- host ------------------------------------------------------
static float* sym_addr_f(const void* symbol) {
    void* p = nullptr;
    cudaGetSymbolAddress(&p, symbol);
    return (float*)p;
}
static __nv_bfloat16* sym_addr_b(const void* symbol) {
    void* p = nullptr;
    cudaGetSymbolAddress(&p, symbol);
    return (__nv_bfloat16*)p;
}

extern "C" void kernel_launch(void* const* d_in, const int* in_sizes, int n_in,
                              void* d_out, int out_size) {
    const float* x     = (const float*)d_in[0];
    const float* qp    = (const float*)d_in[1];
    const float* kp    = (const float*)d_in[2];
    const float* wv    = (const float*)d_in[3];
    const float* wproj = (const float*)d_in[4];
    const float* qgain = (const float*)d_in[5];
    const float* ew0   = (const float*)d_in[6];
    const float* g1    = (const float*)d_in[7];
    const float* b1    = (const float*)d_in[8];
    const float* ew1   = (const float*)d_in[9];
    const float* g2    = (const float*)d_in[10];
    const float* b2    = (const float*)d_in[11];
    const float* ew2   = (const float*)d_in[12];
    const float* ewout = (const float*)d_in[13];
    const float* ct    = (const float*)d_in[14];
    float* z = (float*)d_out;

    float* qkraw = sym_addr_f(g_qkraw);
    float* v     = sym_addr_f(g_v);
    float* h     = sym_addr_f(g_h);
    float* he0   = sym_addr_f(g_he0);
    float* he1   = sym_addr_f(g_he1);
    float* he2   = sym_addr_f(g_he2);

    __nv_bfloat16* a16    = sym_addr_b(g_a16);
    __nv_bfloat16* b16    = sym_addr_b(g_b16);
    __nv_bfloat16* wqkv16 = sym_addr_b(g_w16qkv);
    __nv_bfloat16* wp16   = sym_addr_b(g_w16p);
    __nv_bfloat16* we016  = sym_addr_b(g_w16e0);
    __nv_bfloat16* we116  = sym_addr_b(g_w16e1);
    __nv_bfloat16* we216  = sym_addr_b(g_w16e2);

    cudaFuncSetAttribute(gemm_mma_kernel,
                         cudaFuncAttributeMaxDynamicSharedMemorySize, GSMEM);
    cudaFuncSetAttribute(attn_mma_kernel,
                         cudaFuncAttributeMaxDynamicSharedMemorySize, ATT_SMEM);

    dim3 ggrid(4, 32);    // N=512 GEMMs
    dim3 gqkv(8, 32);     // fused N=1024 qk|v GEMM

    mega_act_kernel<<<2048, 256>>>(x);                                                // 0
    mega_w_kernel<<<6272, 256>>>(qp, kp, wv, wproj, ew0, ew1, ew2);                   // 1
    gemm_mma_kernel<<<gqkv, 256, GSMEM>>>(a16, wqkv16, nullptr, qkraw, v, nullptr, 3);// 2
    rope_kernel<<<4096, 256>>>(qkraw, qgain);                                         // 3 <- profiled
    attn_mma_kernel<<<dim3(32, 16), 128, ATT_SMEM>>>(b16);                            // 4
    gemm_mma_kernel<<<ggrid, 256, GSMEM>>>(b16, wp16, x, h, nullptr, a16, 1);         // 5
    gemm_mma_kernel<<<ggrid, 256, GSMEM>>>(a16, we016, nullptr, he0, nullptr, nullptr, 0); // 6
    ln_split_kernel<<<4096, 256>>>(he0, g1, b1, b16);                                 // 7
    gemm_mma_kernel<<<ggrid, 256, GSMEM>>>(b16, we116, h, he1, nullptr, nullptr, 2);  // 8
    ln_split_kernel<<<4096, 256>>>(he1, g2, b2, a16);                                 // 9
    gemm_mma_kernel<<<ggrid, 256, GSMEM>>>(a16, we216, he1, he2, nullptr, nullptr, 2);// 10
    zout_rms_kernel<<<4096, 256>>>(he2, ewout, ct, z);                                // 11
}

// round 14
// speedup vs baseline: 1.8127x; 1.0363x over previous
#include <cuda_runtime.h>
#include <cuda_bf16.h>
#include <math.h>
#include <stdint.h>

#define T_SEQ 2048
#define NTOK  4096
#define DM    512
#define NH    8
#define DH    64
#define DP    32

typedef unsigned long long ull;

// ---------------- mma / async helpers ----------------------------------------
__device__ __forceinline__ uint32_t smem_u32(const void* p) {
    uint32_t a;
    asm("{ .reg .u64 t; cvta.to.shared.u64 t, %1; cvt.u32.u64 %0, t; }"
        : "=r"(a) : "l"(p));
    return a;
}
__device__ __forceinline__ void cp16(uint32_t dst, const void* src) {
    asm volatile("cp.async.cg.shared.global [%0], [%1], 16;"
        :: "r"(dst), "l"(src) : "memory");
}
__device__ __forceinline__ void ldsm4(uint32_t& r0, uint32_t& r1, uint32_t& r2,
                                      uint32_t& r3, uint32_t addr) {
    asm volatile("ldmatrix.sync.aligned.m8n8.x4.shared.b16 {%0,%1,%2,%3}, [%4];"
        : "=r"(r0), "=r"(r1), "=r"(r2), "=r"(r3) : "r"(addr));
}
__device__ __forceinline__ void mma16816(float& c0, float& c1, float& c2, float& c3,
                                         uint32_t a0, uint32_t a1, uint32_t a2,
                                         uint32_t a3, uint32_t b0, uint32_t b1) {
    asm volatile("mma.sync.aligned.m16n8k16.row.col.f32.bf16.bf16.f32 "
        "{%0,%1,%2,%3}, {%4,%5,%6,%7}, {%8,%9}, {%0,%1,%2,%3};"
        : "+f"(c0), "+f"(c1), "+f"(c2), "+f"(c3)
        : "r"(a0), "r"(a1), "r"(a2), "r"(a3), "r"(b0), "r"(b1));
}

// ---------------- scratch (device globals) ----------------------------------
__device__ __align__(16) float g_qkraw[NTOK * 512];
__device__ __align__(16) float g_v[NTOK * DM];
__device__ __align__(16) float g_h[NTOK * DM];
__device__ __align__(16) float g_he0[NTOK * DM];
__device__ __align__(16) float g_he1[NTOK * DM];
__device__ __align__(16) float g_he2[NTOK * DM];
__device__ __align__(16) float g_cos[T_SEQ * 16];
__device__ __align__(16) float g_sin[T_SEQ * 16];

// q/k bf16 split (compact): [bh][t][64]; q = [qh|ql] (log2e folded), k = [kh|kl]
__device__ __align__(16) __nv_bfloat16 g_qs[16 * T_SEQ * 64];
__device__ __align__(16) __nv_bfloat16 g_ks[16 * T_SEQ * 64];
// transposed V splits: [bh][dim 64][t 2048]
__device__ __align__(16) __nv_bfloat16 g_vth[16 * 64 * T_SEQ];
__device__ __align__(16) __nv_bfloat16 g_vtl[16 * 64 * T_SEQ];

// activation split buffers (compact [hi|lo], 1024 cols)
__device__ __align__(16) __nv_bfloat16 g_a16[NTOK * 1024];
__device__ __align__(16) __nv_bfloat16 g_b16[NTOK * 1024];
// weight split buffers (compact [hi|lo])
__device__ __align__(16) __nv_bfloat16 g_w16qkv[1024 * 1024];  // rows 0-511 qk, 512-1023 v
__device__ __align__(16) __nv_bfloat16 g_w16p[512 * 1024];
__device__ __align__(16) __nv_bfloat16 g_w16e0[512 * 1024];
__device__ __align__(16) __nv_bfloat16 g_w16e1[512 * 1024];
__device__ __align__(16) __nv_bfloat16 g_w16e2[512 * 1024];

// ---------------- activation split of x (vectorized) -------------------------
__global__ __launch_bounds__(256) void mega_act_kernel(const float* __restrict__ x) {
    int idx4 = blockIdx.x * 256 + threadIdx.x;
    int row = idx4 >> 7, c = (idx4 & 127) * 4;
    float4 v = *(const float4*)(x + (size_t)row * 512 + c);
    size_t base = (size_t)row * 1024 + c;
    __nv_bfloat162 h01 = __floats2bfloat162_rn(v.x, v.y);
    __nv_bfloat162 h23 = __floats2bfloat162_rn(v.z, v.w);
    __nv_bfloat162 l01 = __floats2bfloat162_rn(v.x - __bfloat162float(h01.x),
                                               v.y - __bfloat162float(h01.y));
    __nv_bfloat162 l23 = __floats2bfloat162_rn(v.z - __bfloat162float(h23.x),
                                               v.w - __bfloat162float(h23.y));
    *(__nv_bfloat162*)(g_a16 + base) = h01;
    *(__nv_bfloat162*)(g_a16 + base + 2) = h23;
    *(__nv_bfloat162*)(g_a16 + base + 512) = l01;
    *(__nv_bfloat162*)(g_a16 + base + 514) = l23;
}

// ---------------- weight splits ----------------------------------------------
__global__ __launch_bounds__(256) void mega_w_kernel(
    const float* __restrict__ qp, const float* __restrict__ kp,
    const float* __restrict__ wv, const float* __restrict__ wproj,
    const float* __restrict__ ew0, const float* __restrict__ ew1,
    const float* __restrict__ ew2)
{
    int blk = blockIdx.x, tid = threadIdx.x;
    if (blk < 2048) {
        int idx = blk * 256 + tid;
        int row = idx >> 9, col = idx & 511;
        float v;
        if (row < 512) {
            const float* s = (row < 256) ? qp : kp;
            int nn = row & 255;
            int hh = nn >> 5, o = nn & 31;
            v = s[hh * 16384 + col * 32 + o];
        } else {
            v = wv[(size_t)(row - 512) * 512 + col];
        }
        __nv_bfloat16 h = __float2bfloat16(v);
        size_t base = (size_t)row * 1024;
        g_w16qkv[base + col] = h;
        g_w16qkv[base + 512 + col] = __float2bfloat16(v - __bfloat162float(h));
        return;
    }
    const float* src; __nv_bfloat16* dst;
    int idx;
    if (blk < 3072)      { src = wproj; dst = g_w16p;  idx = (blk - 2048) * 256 + tid; }
    else if (blk < 4096) { src = ew0;   dst = g_w16e0; idx = (blk - 3072) * 256 + tid; }
    else if (blk < 5120) { src = ew1;   dst = g_w16e1; idx = (blk - 4096) * 256 + tid; }
    else                 { src = ew2;   dst = g_w16e2; idx = (blk - 5120) * 256 + tid; }
    int row = idx >> 9, col = idx & 511;
    float v = src[idx];
    __nv_bfloat16 h = __float2bfloat16(v);
    size_t base = (size_t)row * 1024;
    dst[base + col] = h;
    dst[base + 512 + col] = __float2bfloat16(v - __bfloat162float(h));
}

// ---------------- trig table --------------------------------------------------
__global__ void trig_kernel() {
    int idx = blockIdx.x * 256 + threadIdx.x;
    if (idx >= T_SEQ * 16) return;
    int t = idx >> 4, i = idx & 15;
    double p = pow(10000.0, (double)i / 16.0);
    float pf = (float)p;
    float freq = 1.0f / pf;
    float ang = (float)t * freq;
    g_cos[idx] = (float)cos((double)ang);
    g_sin[idx] = (float)sin((double)ang);
}

// ---------------- HMMA GEMM (128x128 tile, 2-stage cp.async) -----------------
// epi: 0 none, 1 C=R+acc, 2 C=R+silu(acc), 3 qkv mode (bn<512 -> C fp32;
//      bn>=512 -> C2 fp32 + transposed split to g_vth/g_vtl via smem).
#define NKT 24
#define STG 32768
#define GSMEM (2 * STG)
__global__ __launch_bounds__(256) void gemm_mma_kernel(
    const __nv_bfloat16* __restrict__ A16, const __nv_bfloat16* __restrict__ W16,
    const float* __restrict__ R, float* __restrict__ C, float* __restrict__ C2,
    __nv_bfloat16* __restrict__ S, int epi)
{
    extern __shared__ __align__(128) char sm[];
    uint32_t sb = smem_u32(sm);

    int tid = threadIdx.x, wid = tid >> 5, lane = tid & 31;
    int bm = blockIdx.y * 128, bn = blockIdx.x * 128;
    int wm = wid >> 1, wn = wid & 1;

    const __nv_bfloat16* Abase = A16 + (size_t)bm * 1024;
    const __nv_bfloat16* Wbase = W16 + (size_t)bn * 1024;

    auto load_stage = [&](int kt) {
        uint32_t dA = sb + (uint32_t)(kt & 1) * STG;
        uint32_t dB = dA + 16384;
        int aOff = ((kt < 16) ? kt : kt - 16) * 64;
        int wOff = ((kt < 8) ? kt : kt - 8) * 64;
#pragma unroll
        for (int it = 0; it < 4; it++) {
            int idx = it * 256 + tid, row = idx >> 3, seg = idx & 7;
            uint32_t off = (uint32_t)(row * 128 + ((seg * 16) ^ ((row & 7) << 4)));
            cp16(dA + off, Abase + (size_t)row * 1024 + aOff + seg * 8);
        }
#pragma unroll
        for (int it = 0; it < 4; it++) {
            int idx = it * 256 + tid, row = idx >> 3, seg = idx & 7;
            uint32_t off = (uint32_t)(row * 128 + ((seg * 16) ^ ((row & 7) << 4)));
            cp16(dB + off, Wbase + (size_t)row * 1024 + wOff + seg * 8);
        }
        asm volatile("cp.async.commit_group;" ::: "memory");
    };

    int aRow[2]; uint32_t aSw[2];
#pragma unroll
    for (int mi = 0; mi < 2; mi++) {
        int row = wm * 32 + mi * 16 + (lane & 15);
        aRow[mi] = row;
        aSw[mi] = (uint32_t)((((lane >> 4) << 4)) ^ ((row & 7) << 4));
    }
    int bRow[4]; uint32_t bSw[4];
#pragma unroll
    for (int g = 0; g < 4; g++) {
        int nrow = wn * 64 + g * 16 + (lane & 7) + ((lane >> 4) << 3);
        bRow[g] = nrow;
        bSw[g] = (uint32_t)(((lane & 8) << 1) ^ ((nrow & 7) << 4));
    }

    float c[2][8][4];
#pragma unroll
    for (int mi = 0; mi < 2; mi++)
#pragma unroll
        for (int ni = 0; ni < 8; ni++)
#pragma unroll
            for (int q = 0; q < 4; q++) c[mi][ni][q] = 0.f;

    load_stage(0);

    for (int kt = 0; kt < NKT; kt++) {
        if (kt + 1 < NKT) {
            load_stage(kt + 1);
            asm volatile("cp.async.wait_group 1;" ::: "memory");
        } else {
            asm volatile("cp.async.wait_group 0;" ::: "memory");
        }
        __syncthreads();
        uint32_t base = sb + (uint32_t)(kt & 1) * STG;
        uint32_t baseB = base + 16384;
#pragma unroll
        for (int ks = 0; ks < 4; ks++) {
            uint32_t a0[4], a1[4], b[4][4];
            ldsm4(a0[0], a0[1], a0[2], a0[3],
                  base + (uint32_t)(aRow[0] * 128) + (uint32_t)((ks * 32) ^ aSw[0]));
            ldsm4(a1[0], a1[1], a1[2], a1[3],
                  base + (uint32_t)(aRow[1] * 128) + (uint32_t)((ks * 32) ^ aSw[1]));
#pragma unroll
            for (int g = 0; g < 4; g++)
                ldsm4(b[g][0], b[g][1], b[g][2], b[g][3],
                      baseB + (uint32_t)(bRow[g] * 128) + (uint32_t)((ks * 32) ^ bSw[g]));
#pragma unroll
            for (int g = 0; g < 4; g++) {
                mma16816(c[0][2 * g][0], c[0][2 * g][1], c[0][2 * g][2], c[0][2 * g][3],
                         a0[0], a0[1], a0[2], a0[3], b[g][0], b[g][1]);
                mma16816(c[0][2 * g + 1][0], c[0][2 * g + 1][1], c[0][2 * g + 1][2], c[0][2 * g + 1][3],
                         a0[0], a0[1], a0[2], a0[3], b[g][2], b[g][3]);
                mma16816(c[1][2 * g][0], c[1][2 * g][1], c[1][2 * g][2], c[1][2 * g][3],
                         a1[0], a1[1], a1[2], a1[3], b[g][0], b[g][1]);
                mma16816(c[1][2 * g + 1][0], c[1][2 * g + 1][1], c[1][2 * g + 1][2], c[1][2 * g + 1][3],
                         a1[0], a1[1], a1[2], a1[3], b[g][2], b[g][3]);
            }
        }
        if (kt + 1 < NKT) __syncthreads();
    }

    int gq = lane >> 2, tig = lane & 3;

    if (epi == 3 && bn >= 512) {
        // ---- V half: fp32 write + transposed split via smem ----
        __syncthreads();
        float* smt = (float*)sm;            // [col 128][row 128] fp32
#pragma unroll
        for (int mi = 0; mi < 2; mi++) {
#pragma unroll
            for (int ni = 0; ni < 8; ni++) {
#pragma unroll
                for (int half = 0; half < 2; half++) {
                    int row = wm * 32 + mi * 16 + gq + half * 8;
                    int colL = wn * 64 + ni * 8 + tig * 2;
                    float v0 = c[mi][ni][half * 2], v1 = c[mi][ni][half * 2 + 1];
                    float2 ov = {v0, v1};
                    *(float2*)(C2 + (size_t)(bm + row) * 512 + (bn - 512) + colL) = ov;
                    smt[colL * 128 + row] = v0;
                    smt[(colL + 1) * 128 + row] = v1;
                }
            }
        }
        __syncthreads();
        int colL = tid >> 1, th = (tid & 1) * 64;
        int vcol = (bn - 512) + colL;
        int hh = vcol >> 6, d = vcol & 63;
        int bq = bm >> 11, tloc = bm & 2047;
        __nv_bfloat16* oh = g_vth + (((size_t)(bq * 8 + hh) * 64 + d) * 2048) + tloc + th;
        __nv_bfloat16* ol = g_vtl + (((size_t)(bq * 8 + hh) * 64 + d) * 2048) + tloc + th;
        const float* src = smt + colL * 128 + th;
#pragma unroll
        for (int j8 = 0; j8 < 8; j8++) {
            float4 v0 = *(const float4*)(src + j8 * 8);
            float4 v1 = *(const float4*)(src + j8 * 8 + 4);
            __nv_bfloat162 hv[4], lv[4];
            hv[0] = __floats2bfloat162_rn(v0.x, v0.y);
            hv[1] = __floats2bfloat162_rn(v0.z, v0.w);
            hv[2] = __floats2bfloat162_rn(v1.x, v1.y);
            hv[3] = __floats2bfloat162_rn(v1.z, v1.w);
            lv[0] = __floats2bfloat162_rn(v0.x - __bfloat162float(hv[0].x),
                                          v0.y - __bfloat162float(hv[0].y));
            lv[1] = __floats2bfloat162_rn(v0.z - __bfloat162float(hv[1].x),
                                          v0.w - __bfloat162float(hv[1].y));
            lv[2] = __floats2bfloat162_rn(v1.x - __bfloat162float(hv[2].x),
                                          v1.y - __bfloat162float(hv[2].y));
            lv[3] = __floats2bfloat162_rn(v1.z - __bfloat162float(hv[3].x),
                                          v1.w - __bfloat162float(hv[3].y));
            *(uint4*)(oh + j8 * 8) = *(uint4*)hv;
            *(uint4*)(ol + j8 * 8) = *(uint4*)lv;
        }
        return;
    }

    float* Cout = C;
    int bncol = bn;
#pragma unroll
    for (int mi = 0; mi < 2; mi++) {
#pragma unroll
        for (int ni = 0; ni < 8; ni++) {
#pragma unroll
            for (int half = 0; half < 2; half++) {
                int row = bm + wm * 32 + mi * 16 + gq + half * 8;
                int col = bncol + wn * 64 + ni * 8 + tig * 2;
                size_t o = (size_t)row * 512 + col;
                float v0 = c[mi][ni][half * 2], v1 = c[mi][ni][half * 2 + 1];
                if (epi == 1) {
                    float2 rr = *(const float2*)(R + o);
                    v0 += rr.x; v1 += rr.y;
                } else if (epi == 2) {
                    float2 rr = *(const float2*)(R + o);
                    v0 = rr.x + v0 / (1.0f + expf(-v0));
                    v1 = rr.y + v1 / (1.0f + expf(-v1));
                }
                if (Cout) {
                    float2 ov = {v0, v1};
                    *(float2*)(Cout + o) = ov;
                }
                if (S) {
                    __nv_bfloat16 h0 = __float2bfloat16(v0);
                    __nv_bfloat16 h1 = __float2bfloat16(v1);
                    __nv_bfloat16 l0 = __float2bfloat16(v0 - __bfloat162float(h0));
                    __nv_bfloat16 l1 = __float2bfloat16(v1 - __bfloat162float(h1));
                    size_t sbase = (size_t)row * 1024 + col;
                    __nv_bfloat162 hh; hh.x = h0; hh.y = h1;
                    __nv_bfloat162 ll; ll.x = l0; ll.y = l1;
                    *(__nv_bfloat162*)(S + sbase) = hh;
                    *(__nv_bfloat162*)(S + sbase + 512) = ll;
                }
            }
        }
    }
}

// ---------------- RoPE (log2e folded into q) ---------------------------------
__global__ __launch_bounds__(256) void rope_kernel(const float* __restrict__ qkraw,
                                                   const float* __restrict__ gain) {
    int token = blockIdx.x;
    int b = token >> 11, t = token & 2047;
    int tid = threadIdx.x;
    int h = tid >> 5, o = tid & 31, i = o & 15;
    float c = g_cos[t * 16 + i];
    float s = g_sin[t * 16 + i];
    const float* row = qkraw + (size_t)token * 512;

    float q1 = row[h * 32 + i], q2 = row[h * 32 + i + 16];
    float qv = (o < 16) ? (q1 * c - q2 * s) : (q2 * c + q1 * s);
    qv *= gain[h] * 0.17677669529663687f * 1.4426950408889634f;  // /sqrt(32) * log2e

    float k1 = row[256 + h * 32 + i], k2 = row[256 + h * 32 + i + 16];
    float kv = (o < 16) ? (k1 * c - k2 * s) : (k2 * c + k1 * s);

    size_t base = ((size_t)(b * 8 + h) * T_SEQ + t) * 64;
    __nv_bfloat16 qh = __float2bfloat16(qv);
    g_qs[base + o] = qh;
    g_qs[base + 32 + o] = __float2bfloat16(qv - __bfloat162float(qh));

    __nv_bfloat16 kh = __float2bfloat16(kv);
    g_ks[base + o] = kh;
    g_ks[base + 32 + o] = __float2bfloat16(kv - __bfloat162float(kh));
}

// ---------------- MMA flash attention (compact q/k, exp2 softmax) ------------
#define ATT_STG 24576
#define ATT_SMEM 49152
__global__ __launch_bounds__(128, 3) void attn_mma_kernel(__nv_bfloat16* __restrict__ Y16) {
    extern __shared__ __align__(128) char smA[];
    uint32_t sb = smem_u32(smA);

    int tid = threadIdx.x, wid = tid >> 5, lane = tid & 31;
    int gq = lane >> 2, tig = lane & 3;
    int bh = blockIdx.y, b = bh >> 3, h = bh & 7;
    int tileIdx = (int)gridDim.x - 1 - (int)blockIdx.x;  // heavy first
    int tb = tileIdx * 64;

    const __nv_bfloat16* Kg = g_ks + (size_t)bh * T_SEQ * 64;
    const __nv_bfloat16* Vhg = g_vth + (size_t)bh * 64 * T_SEQ;
    const __nv_bfloat16* Vlg = g_vtl + (size_t)bh * 64 * T_SEQ;

    {
        const __nv_bfloat16* Qg = g_qs + ((size_t)bh * T_SEQ + tb) * 64;
        int row = tid >> 1, sbase = (tid & 1) * 4;
#pragma unroll
        for (int s = 0; s < 4; s++) {
            int seg = sbase + s;
            cp16(sb + ATT_STG + (uint32_t)(row * 128 + ((seg * 16) ^ ((row & 7) << 4))),
                 Qg + (size_t)row * 64 + seg * 8);
        }
        asm volatile("cp.async.commit_group;" ::: "memory");
    }

    auto load_kv = [&](int t) {
        uint32_t st = sb + (uint32_t)(t & 1) * ATT_STG;
        int j0 = t * 64;
        int row = tid >> 1;
        int sbase = (tid & 1) * 4;
#pragma unroll
        for (int s = 0; s < 4; s++) {
            int seg = sbase + s;
            uint32_t off = (uint32_t)(row * 128 + ((seg * 16) ^ ((row & 7) << 4)));
            cp16(st + off, Kg + (size_t)(j0 + row) * 64 + seg * 8);
            cp16(st + 8192 + off, Vhg + (size_t)row * T_SEQ + j0 + seg * 8);
            cp16(st + 16384 + off, Vlg + (size_t)row * T_SEQ + j0 + seg * 8);
        }
        asm volatile("cp.async.commit_group;" ::: "memory");
    };

    load_kv(0);

    uint32_t qa[4][4];
    {
        asm volatile("cp.async.wait_group 1;" ::: "memory");
        __syncthreads();
        int qrow = wid * 16 + (lane & 15);
        uint32_t qbase = sb + ATT_STG + (uint32_t)(qrow * 128);
        uint32_t qxor = (uint32_t)((lane >> 4) << 4);
        uint32_t rxor = (uint32_t)((qrow & 7) << 4);
#pragma unroll
        for (int cidx = 0; cidx < 4; cidx++)
            ldsm4(qa[cidx][0], qa[cidx][1], qa[cidx][2], qa[cidx][3],
                  qbase + (uint32_t)(((cidx * 32) + qxor) ^ rxor));
        __syncthreads();
    }

    float o[8][4];
#pragma unroll
    for (int n = 0; n < 8; n++)
#pragma unroll
        for (int q = 0; q < 4; q++) o[n][q] = 0.f;
    float mLo = -3.0e38f, mHi = -3.0e38f, lLo = 0.f, lHi = 0.f;

    int nRow[4]; uint32_t nSw[4];
#pragma unroll
    for (int g = 0; g < 4; g++) {
        int nr = g * 16 + (lane & 7) + ((lane >> 4) << 3);
        nRow[g] = nr;
        nSw[g] = (uint32_t)(((lane & 8) << 1));
    }

    const int qi[6]   = {0, 1, 2, 3, 0, 1};
    const int koff[6] = {0, 32, 0, 32, 64, 96};

    int ntk = tileIdx + 1;
    int wminr = tb + wid * 16;

    for (int t = 0; t < ntk; t++) {
        int j0 = t * 64;
        if (t + 1 < ntk) {
            load_kv(t + 1);
            asm volatile("cp.async.wait_group 1;" ::: "memory");
        } else {
            asm volatile("cp.async.wait_group 0;" ::: "memory");
        }
        __syncthreads();
        uint32_t stage = sb + (uint32_t)(t & 1) * ATT_STG;
        uint32_t smK = stage, smVh = stage + 8192, smVl = stage + 16384;

        if (j0 <= wminr + 15) {
            float s[8][4];
#pragma unroll
            for (int n = 0; n < 8; n++)
#pragma unroll
                for (int q = 0; q < 4; q++) s[n][q] = 0.f;

#pragma unroll
            for (int kk = 0; kk < 6; kk++) {
                const uint32_t* qf = qa[qi[kk]];
#pragma unroll
                for (int g = 0; g < 4; g++) {
                    uint32_t kb[4];
                    uint32_t ka = smK + (uint32_t)(nRow[g] * 128)
                                + (uint32_t)((koff[kk] + nSw[g]) ^ ((nRow[g] & 7) << 4));
                    ldsm4(kb[0], kb[1], kb[2], kb[3], ka);
                    mma16816(s[2 * g][0], s[2 * g][1], s[2 * g][2], s[2 * g][3],
                             qf[0], qf[1], qf[2], qf[3], kb[0], kb[1]);
                    mma16816(s[2 * g + 1][0], s[2 * g + 1][1], s[2 * g + 1][2], s[2 * g + 1][3],
                             qf[0], qf[1], qf[2], qf[3], kb[2], kb[3]);
                }
            }

            int rowLo = tb + wid * 16 + gq;
            int rowHi = rowLo + 8;
            if (j0 + 63 > wminr) {
#pragma unroll
                for (int n = 0; n < 8; n++) {
                    int k0 = j0 + n * 8 + tig * 2;
                    if (k0 > rowLo)     s[n][0] = -1.0e30f;
                    if (k0 + 1 > rowLo) s[n][1] = -1.0e30f;
                    if (k0 > rowHi)     s[n][2] = -1.0e30f;
                    if (k0 + 1 > rowHi) s[n][3] = -1.0e30f;
                }
            }

            float cLo = -3.0e38f, cHi = -3.0e38f;
#pragma unroll
            for (int n = 0; n < 8; n++) {
                cLo = fmaxf(cLo, fmaxf(s[n][0], s[n][1]));
                cHi = fmaxf(cHi, fmaxf(s[n][2], s[n][3]));
            }
            cLo = fmaxf(cLo, __shfl_xor_sync(0xffffffffu, cLo, 1));
            cLo = fmaxf(cLo, __shfl_xor_sync(0xffffffffu, cLo, 2));
            cHi = fmaxf(cHi, __shfl_xor_sync(0xffffffffu, cHi, 1));
            cHi = fmaxf(cHi, __shfl_xor_sync(0xffffffffu, cHi, 2));
            float mnLo = fmaxf(mLo, cLo), mnHi = fmaxf(mHi, cHi);
            float corrLo = exp2f(mLo - mnLo), corrHi = exp2f(mHi - mnHi);
            mLo = mnLo; mHi = mnHi;
            lLo *= corrLo; lHi *= corrHi;
#pragma unroll
            for (int n = 0; n < 8; n++) {
                o[n][0] *= corrLo; o[n][1] *= corrLo;
                o[n][2] *= corrHi; o[n][3] *= corrHi;
            }

            uint32_t ph[8][2], pl[8][2];
            float psLo = 0.f, psHi = 0.f;
#pragma unroll
            for (int n = 0; n < 8; n++) {
                float p0 = exp2f(s[n][0] - mLo), p1 = exp2f(s[n][1] - mLo);
                float p2 = exp2f(s[n][2] - mHi), p3 = exp2f(s[n][3] - mHi);
                psLo += p0 + p1; psHi += p2 + p3;
                __nv_bfloat162 h01 = __floats2bfloat162_rn(p0, p1);
                __nv_bfloat162 h23 = __floats2bfloat162_rn(p2, p3);
                __nv_bfloat162 l01 = __floats2bfloat162_rn(p0 - __bfloat162float(h01.x),
                                                           p1 - __bfloat162float(h01.y));
                __nv_bfloat162 l23 = __floats2bfloat162_rn(p2 - __bfloat162float(h23.x),
                                                           p3 - __bfloat162float(h23.y));
                ph[n][0] = *(uint32_t*)&h01; ph[n][1] = *(uint32_t*)&h23;
                pl[n][0] = *(uint32_t*)&l01; pl[n][1] = *(uint32_t*)&l23;
            }
            lLo += psLo; lHi += psHi;

#pragma unroll
            for (int kk = 0; kk < 4; kk++) {
#pragma unroll
                for (int g = 0; g < 4; g++) {
                    uint32_t roff = (uint32_t)(nRow[g] * 128);
                    uint32_t xoff = (uint32_t)(((kk * 32) + nSw[g]) ^ ((nRow[g] & 7) << 4));
                    uint32_t vb[4];
                    ldsm4(vb[0], vb[1], vb[2], vb[3], smVh + roff + xoff);
                    mma16816(o[2 * g][0], o[2 * g][1], o[2 * g][2], o[2 * g][3],
                             ph[2 * kk][0], ph[2 * kk][1], ph[2 * kk + 1][0], ph[2 * kk + 1][1],
                             vb[0], vb[1]);
                    mma16816(o[2 * g + 1][0], o[2 * g + 1][1], o[2 * g + 1][2], o[2 * g + 1][3],
                             ph[2 * kk][0], ph[2 * kk][1], ph[2 * kk + 1][0], ph[2 * kk + 1][1],
                             vb[2], vb[3]);
                    mma16816(o[2 * g][0], o[2 * g][1], o[2 * g][2], o[2 * g][3],
                             pl[2 * kk][0], pl[2 * kk][1], pl[2 * kk + 1][0], pl[2 * kk + 1][1],
                             vb[0], vb[1]);
                    mma16816(o[2 * g + 1][0], o[2 * g + 1][1], o[2 * g + 1][2], o[2 * g + 1][3],
                             pl[2 * kk][0], pl[2 * kk][1], pl[2 * kk + 1][0], pl[2 * kk + 1][1],
                             vb[2], vb[3]);
                    uint32_t vc[4];
                    ldsm4(vc[0], vc[1], vc[2], vc[3], smVl + roff + xoff);
                    mma16816(o[2 * g][0], o[2 * g][1], o[2 * g][2], o[2 * g][3],
                             ph[2 * kk][0], ph[2 * kk][1], ph[2 * kk + 1][0], ph[2 * kk + 1][1],
                             vc[0], vc[1]);
                    mma16816(o[2 * g + 1][0], o[2 * g + 1][1], o[2 * g + 1][2], o[2 * g + 1][3],
                             ph[2 * kk][0], ph[2 * kk][1], ph[2 * kk + 1][0], ph[2 * kk + 1][1],
                             vc[2], vc[3]);
                }
            }
        }
        if (t + 1 < ntk) __syncthreads();
    }

    lLo += __shfl_xor_sync(0xffffffffu, lLo, 1);
    lLo += __shfl_xor_sync(0xffffffffu, lLo, 2);
    lHi += __shfl_xor_sync(0xffffffffu, lHi, 1);
    lHi += __shfl_xor_sync(0xffffffffu, lHi, 2);

#pragma unroll
    for (int hq = 0; hq < 2; hq++) {
        int row = tb + wid * 16 + gq + hq * 8;
        float linv = 1.0f / (hq ? lHi : lLo);
        int tok = b * T_SEQ + row;
        const float* vr = g_v + (size_t)tok * 512 + h * 64;
        float y0[8], y1[8];
        float2 vv[8];
        float n2 = 0.f, pr = 0.f;
#pragma unroll
        for (int n = 0; n < 8; n++) {
            vv[n] = *(const float2*)(vr + n * 8 + tig * 2);
            y0[n] = o[n][hq * 2] * linv;
            y1[n] = o[n][hq * 2 + 1] * linv;
            n2 += vv[n].x * vv[n].x + vv[n].y * vv[n].y;
            pr += y0[n] * vv[n].x + y1[n] * vv[n].y;
        }
        n2 += __shfl_xor_sync(0xffffffffu, n2, 1);
        n2 += __shfl_xor_sync(0xffffffffu, n2, 2);
        pr += __shfl_xor_sync(0xffffffffu, pr, 1);
        pr += __shfl_xor_sync(0xffffffffu, pr, 2);
        float rn = 1.0f / fmaxf(sqrtf(n2), 1e-12f);
        float prn = pr * rn * rn;
        size_t obase = (size_t)tok * 1024 + h * 64;
#pragma unroll
        for (int n = 0; n < 8; n++) {
            float a0 = y0[n] - prn * vv[n].x;
            float a1 = y1[n] - prn * vv[n].y;
            __nv_bfloat16 h0 = __float2bfloat16(a0);
            __nv_bfloat16 h1 = __float2bfloat16(a1);
            __nv_bfloat162 hh; hh.x = h0; hh.y = h1;
            __nv_bfloat162 ll;
            ll.x = __float2bfloat16(a0 - __bfloat162float(h0));
            ll.y = __float2bfloat16(a1 - __bfloat162float(h1));
            size_t p = obase + n * 8 + tig * 2;
            *(__nv_bfloat162*)(Y16 + p) = hh;
            *(__nv_bfloat162*)(Y16 + p + 512) = ll;
        }
    }
}

// ---------------- layernorm with split-bf16 output --------------------------
__global__ __launch_bounds__(256) void ln_split_kernel(const float* __restrict__ in,
                                                       const float* __restrict__ g,
                                                       const float* __restrict__ b,
                                                       __nv_bfloat16* __restrict__ S) {
    int row = blockIdx.x, tid = threadIdx.x;
    const float* rp = in + (size_t)row * 512;
    float a0 = rp[tid], a1 = rp[tid + 256];
    float s = a0 + a1, s2 = a0 * a0 + a1 * a1;
#pragma unroll
    for (int off = 16; off; off >>= 1) {
        s  += __shfl_down_sync(0xffffffffu, s, off);
        s2 += __shfl_down_sync(0xffffffffu, s2, off);
    }
    __shared__ float rs[8], rs2[8];
    __shared__ float mean_s, inv_s;
    if ((tid & 31) == 0) { rs[tid >> 5] = s; rs2[tid >> 5] = s2; }
    __syncthreads();
    if (tid == 0) {
        float S0 = 0, S2 = 0;
#pragma unroll
        for (int w = 0; w < 8; w++) { S0 += rs[w]; S2 += rs2[w]; }
        float m = S0 * (1.0f / 512.0f);
        float var = fmaxf(S2 * (1.0f / 512.0f) - m * m, 0.0f);
        mean_s = m;
        inv_s = rsqrtf(var + 1e-5f);
    }
    __syncthreads();
    float v0 = (a0 - mean_s) * inv_s * g[tid] + b[tid];
    float v1 = (a1 - mean_s) * inv_s * g[tid + 256] + b[tid + 256];
    size_t base = (size_t)row * 1024;
    __nv_bfloat16 h0 = __float2bfloat16(v0);
    __nv_bfloat16 h1 = __float2bfloat16(v1);
    S[base + tid] = h0;
    S[base + 512 + tid] = __float2bfloat16(v0 - __bfloat162float(h0));
    S[base + tid + 256] = h1;
    S[base + 512 + tid + 256] = __float2bfloat16(v1 - __bfloat162float(h1));
}

// ---------------- fused rms + final projection + tanh ------------------------
__global__ __launch_bounds__(256) void zout_rms_kernel(const float* __restrict__ he2,
                                                       const float* __restrict__ wout,
                                                       const float* __restrict__ ct,
                                                       float* __restrict__ z) {
    int token = blockIdx.x, tid = threadIdx.x;
    __shared__ float xs[512];
    __shared__ float ps[256];
    __shared__ float rs2[8];
    __shared__ float inv_s;
    const float* rp = he2 + (size_t)token * 512;
    float a0 = rp[tid], a1 = rp[tid + 256];
    xs[tid] = a0;
    xs[tid + 256] = a1;
    float s2 = a0 * a0 + a1 * a1;
#pragma unroll
    for (int off = 16; off; off >>= 1) s2 += __shfl_down_sync(0xffffffffu, s2, off);
    if ((tid & 31) == 0) rs2[tid >> 5] = s2;
    __syncthreads();
    if (tid == 0) {
        float S2 = 0;
#pragma unroll
        for (int w = 0; w < 8; w++) S2 += rs2[w];
        inv_s = rsqrtf(S2 * (1.0f / 512.0f) + 1e-6f);
    }
    __syncthreads();
    int n = tid & 31, g = tid >> 5;
    const float* wr = wout + n * 512 + g * 64;
    const float* xr = xs + g * 64;
    float p = 0.f;
#pragma unroll
    for (int d = 0; d < 64; d++) p += xr[d] * wr[d];
    ps[tid] = p;
    __syncthreads();
    if (tid < 32) {
        float s = 0.f;
#pragma unroll
        for (int gg = 0; gg < 8; gg++) s += ps[gg * 32 + tid];
        s *= inv_s;
        float c = ct[tid];
        float sp = log1pf(expf(c));
        z[(size_t)token * 32 + tid] = tanhf(s / (sp + 1e-4f));
    }
}

// ---------------- host ------------------------------------------------------
static float* sym_addr_f(const void* symbol) {
    void* p = nullptr;
    cudaGetSymbolAddress(&p, symbol);
    return (float*)p;
}
static __nv_bfloat16* sym_addr_b(const void* symbol) {
    void* p = nullptr;
    cudaGetSymbolAddress(&p, symbol);
    return (__nv_bfloat16*)p;
}

extern "C" void kernel_launch(void* const* d_in, const int* in_sizes, int n_in,
                              void* d_out, int out_size) {
    const float* x     = (const float*)d_in[0];
    const float* qp    = (const float*)d_in[1];
    const float* kp    = (const float*)d_in[2];
    const float* wv    = (const float*)d_in[3];
    const float* wproj = (const float*)d_in[4];
    const float* qgain = (const float*)d_in[5];
    const float* ew0   = (const float*)d_in[6];
    const float* g1    = (const float*)d_in[7];
    const float* b1    = (const float*)d_in[8];
    const float* ew1   = (const float*)d_in[9];
    const float* g2    = (const float*)d_in[10];
    const float* b2    = (const float*)d_in[11];
    const float* ew2   = (const float*)d_in[12];
    const float* ewout = (const float*)d_in[13];
    const float* ct    = (const float*)d_in[14];
    float* z = (float*)d_out;

    float* qkraw = sym_addr_f(g_qkraw);
    float* v     = sym_addr_f(g_v);
    float* h     = sym_addr_f(g_h);
    float* he0   = sym_addr_f(g_he0);
    float* he1   = sym_addr_f(g_he1);
    float* he2   = sym_addr_f(g_he2);

    __nv_bfloat16* a16    = sym_addr_b(g_a16);
    __nv_bfloat16* b16    = sym_addr_b(g_b16);
    __nv_bfloat16* wqkv16 = sym_addr_b(g_w16qkv);
    __nv_bfloat16* wp16   = sym_addr_b(g_w16p);
    __nv_bfloat16* we016  = sym_addr_b(g_w16e0);
    __nv_bfloat16* we116  = sym_addr_b(g_w16e1);
    __nv_bfloat16* we216  = sym_addr_b(g_w16e2);

    cudaFuncSetAttribute(gemm_mma_kernel,
                         cudaFuncAttributeMaxDynamicSharedMemorySize, GSMEM);
    cudaFuncSetAttribute(attn_mma_kernel,
                         cudaFuncAttributeMaxDynamicSharedMemorySize, ATT_SMEM);

    dim3 ggrid(4, 32);    // N=512 GEMMs
    dim3 gqkv(8, 32);     // fused N=1024 qk|v GEMM

    mega_act_kernel<<<2048, 256>>>(x);                                                // 0
    mega_w_kernel<<<6144, 256>>>(qp, kp, wv, wproj, ew0, ew1, ew2);                   // 1
    trig_kernel<<<128, 256>>>();                                                      // 2
    gemm_mma_kernel<<<gqkv, 256, GSMEM>>>(a16, wqkv16, nullptr, qkraw, v, nullptr, 3);// 3 <- profiled
    rope_kernel<<<4096, 256>>>(qkraw, qgain);                                         // 4
    attn_mma_kernel<<<dim3(32, 16), 128, ATT_SMEM>>>(b16);                            // 5
    gemm_mma_kernel<<<ggrid, 256, GSMEM>>>(b16, wp16, x, h, nullptr, a16, 1);         // 6
    gemm_mma_kernel<<<ggrid, 256, GSMEM>>>(a16, we016, nullptr, he0, nullptr, nullptr, 0); // 7
    ln_split_kernel<<<4096, 256>>>(he0, g1, b1, b16);                                 // 8
    gemm_mma_kernel<<<ggrid, 256, GSMEM>>>(b16, we116, h, he1, nullptr, nullptr, 2);  // 9
    ln_split_kernel<<<4096, 256>>>(he1, g2, b2, a16);                                 // 10
    gemm_mma_kernel<<<ggrid, 256, GSMEM>>>(a16, we216, he1, he2, nullptr, nullptr, 2);// 11
    zout_rms_kernel<<<4096, 256>>>(he2, ewout, ct, z);                                // 12
}